// round 5
// baseline (speedup 1.0000x reference)
#include <cuda_runtime.h>
#include <math.h>

// Problem constants (fixed shapes from reference)
#define T_TOK 8192          // 4 * 2048 tokens
#define HDIM  2048
#define FDIM  4096          // 2*H

// ---------------- scratch (static __device__, allocation-guard safe) -------
__device__ int   g_cnt[2];
__device__ int   g_idx[2][T_TOK];
__device__ float g_h[(size_t)T_TOK * FDIM];   // 134 MB intermediate, indexed by token

// ---------------- packed fp32x2 helpers (full-rate FMA on sm_103a) ---------
typedef unsigned long long u64;

__device__ __forceinline__ u64 fma2(u64 a, u64 b, u64 c) {
    u64 d;
    asm("fma.rn.f32x2 %0, %1, %2, %3;" : "=l"(d) : "l"(a), "l"(b), "l"(c));
    return d;
}
__device__ __forceinline__ u64 pack2(float v) {
    u64 d;
    asm("mov.b64 %0, {%1, %1};" : "=l"(d) : "f"(v));
    return d;
}
__device__ __forceinline__ void unpack2(u64 d, float& lo, float& hi) {
    asm("mov.b64 {%0, %1}, %2;" : "=f"(lo), "=f"(hi) : "l"(d));
}

// ---------------- kernels ---------------------------------------------------

__global__ void zero_cnt_kernel() {
    if (threadIdx.x < 2) g_cnt[threadIdx.x] = 0;
}

// Gate: logits = x @ Wg^T, expert = argmax (softmax is monotone; tie -> 0 like jnp.argmax).
// One warp per token. Compact token ids into per-expert lists.
__global__ void gate_kernel(const float* __restrict__ x, const float* __restrict__ Wg) {
    __shared__ float swg[2 * HDIM];
    int tid = threadIdx.x;
    for (int i = tid; i < 2 * HDIM; i += blockDim.x) swg[i] = Wg[i];
    __syncthreads();

    int warp = tid >> 5, lane = tid & 31;
    int tok = blockIdx.x * 8 + warp;
    const float* xr = x + (size_t)tok * HDIM;

    float a0 = 0.f, a1 = 0.f;
    for (int k = lane; k < HDIM; k += 32) {
        float v = xr[k];
        a0 = fmaf(v, swg[k], a0);
        a1 = fmaf(v, swg[HDIM + k], a1);
    }
#pragma unroll
    for (int o = 16; o; o >>= 1) {
        a0 += __shfl_xor_sync(0xffffffffu, a0, o);
        a1 += __shfl_xor_sync(0xffffffffu, a1, o);
    }
    if (lane == 0) {
        int e = (a1 > a0) ? 1 : 0;            // tie -> expert 0 (argmax-first)
        int pos = atomicAdd(&g_cnt[e], 1);
        g_idx[e][pos] = tok;
    }
}

template <int ACT>
__device__ __forceinline__ float act_fn(float v) {
    if (ACT == 0) return 0.5f * v * (1.0f + erff(v * 0.70710678118654752440f)); // exact GELU
    if (ACT == 1) return fmaxf(v, 0.0f);                                        // ReLU
    return v;
}

// Gathered NT GEMM over one expert's compacted token rows.
//   C[tok, nBase+j] = act( sum_k A[tok,k] * B[nBase+j, k] + bias[nBase+j] )
// A: row-major [*, K] (K contiguous), B: row-major [N, K], tile 128x128x16,
// 256 threads, 8x8 per thread, fp32x2 packed-FMA inner loop.
template <int ACT>
__global__ void __launch_bounds__(256, 2)
gemm_moe_kernel(const float* __restrict__ A,
                const float* __restrict__ B,
                const float* __restrict__ bias,
                float* __restrict__ C, int ldc,
                int K, int expert) {
    const int BM = 128, BN = 128, BK = 16;
    __shared__ __align__(16) float As[BK][BM + 4];
    __shared__ __align__(16) float Bs[BK][BN + 4];
    __shared__ int sTok[BM];

    int n_e = g_cnt[expert];
    int mBase = blockIdx.y * BM;
    if (mBase >= n_e) return;
    int nBase = blockIdx.x * BN;

    int tid = threadIdx.x;
    if (tid < BM) {
        int r = mBase + tid;
        sTok[tid] = (r < n_e) ? g_idx[expert][r] : -1;
    }
    __syncthreads();

    int loadRow  = tid >> 1;
    int loadHalf = (tid & 1) * 4;
    const float* aPtr = nullptr;
    {
        int tokL = sTok[loadRow];
        if (tokL >= 0) aPtr = A + (size_t)tokL * (size_t)K + loadHalf;
    }
    const float* bPtr = B + (size_t)(nBase + loadRow) * (size_t)K + loadHalf;

    int tx = tid & 15, ty = tid >> 4;  // 16 x 16 thread grid

    u64 acc[8][4];                     // [row i][col-pair j] packed fp32x2
#pragma unroll
    for (int i = 0; i < 8; ++i)
#pragma unroll
        for (int j = 0; j < 4; ++j) acc[i][j] = 0ull;

    for (int k0 = 0; k0 < K; k0 += BK) {
        float4 av0 = make_float4(0.f, 0.f, 0.f, 0.f), av1 = av0;
        if (aPtr) {
            av0 = *(const float4*)(aPtr + k0);
            av1 = *(const float4*)(aPtr + k0 + 8);
        }
        float4 bv0 = *(const float4*)(bPtr + k0);
        float4 bv1 = *(const float4*)(bPtr + k0 + 8);

        __syncthreads();
        As[loadHalf + 0][loadRow] = av0.x;
        As[loadHalf + 1][loadRow] = av0.y;
        As[loadHalf + 2][loadRow] = av0.z;
        As[loadHalf + 3][loadRow] = av0.w;
        As[loadHalf + 8][loadRow] = av1.x;
        As[loadHalf + 9][loadRow] = av1.y;
        As[loadHalf + 10][loadRow] = av1.z;
        As[loadHalf + 11][loadRow] = av1.w;
        Bs[loadHalf + 0][loadRow] = bv0.x;
        Bs[loadHalf + 1][loadRow] = bv0.y;
        Bs[loadHalf + 2][loadRow] = bv0.z;
        Bs[loadHalf + 3][loadRow] = bv0.w;
        Bs[loadHalf + 8][loadRow] = bv1.x;
        Bs[loadHalf + 9][loadRow] = bv1.y;
        Bs[loadHalf + 10][loadRow] = bv1.z;
        Bs[loadHalf + 11][loadRow] = bv1.w;
        __syncthreads();

#pragma unroll
        for (int k = 0; k < BK; ++k) {
            float4 a0 = *(const float4*)&As[k][ty * 8];
            float4 a1 = *(const float4*)&As[k][ty * 8 + 4];
            double2 b0 = *(const double2*)&Bs[k][tx * 8];
            double2 b1 = *(const double2*)&Bs[k][tx * 8 + 4];
            u64 bp[4];
            bp[0] = __double_as_longlong(b0.x);
            bp[1] = __double_as_longlong(b0.y);
            bp[2] = __double_as_longlong(b1.x);
            bp[3] = __double_as_longlong(b1.y);
            float aa[8] = {a0.x, a0.y, a0.z, a0.w, a1.x, a1.y, a1.z, a1.w};
#pragma unroll
            for (int i = 0; i < 8; ++i) {
                u64 ai = pack2(aa[i]);
#pragma unroll
                for (int j = 0; j < 4; ++j)
                    acc[i][j] = fma2(ai, bp[j], acc[i][j]);
            }
        }
    }

    // Epilogue: bias + activation, coalesced float4 stores per token row.
    float4 bb0 = *(const float4*)(bias + nBase + tx * 8);
    float4 bb1 = *(const float4*)(bias + nBase + tx * 8 + 4);
    float bvals[8] = {bb0.x, bb0.y, bb0.z, bb0.w, bb1.x, bb1.y, bb1.z, bb1.w};

#pragma unroll
    for (int i = 0; i < 8; ++i) {
        int tok = sTok[ty * 8 + i];
        if (tok < 0) continue;
        float v[8];
#pragma unroll
        for (int j = 0; j < 4; ++j) unpack2(acc[i][j], v[2 * j], v[2 * j + 1]);
#pragma unroll
        for (int c = 0; c < 8; ++c) v[c] = act_fn<ACT>(v[c] + bvals[c]);
        float* cp = C + (size_t)tok * (size_t)ldc + nBase + tx * 8;
        *(float4*)cp       = make_float4(v[0], v[1], v[2], v[3]);
        *(float4*)(cp + 4) = make_float4(v[4], v[5], v[6], v[7]);
    }
}

// ---------------- launch -----------------------------------------------------

extern "C" void kernel_launch(void* const* d_in, const int* in_sizes, int n_in,
                              void* d_out, int out_size) {
    (void)in_sizes; (void)n_in; (void)out_size;
    const float* x   = (const float*)d_in[0];
    const float* Wg  = (const float*)d_in[1];
    const float* W0a = (const float*)d_in[2];
    const float* b0a = (const float*)d_in[3];
    const float* W0b = (const float*)d_in[4];
    const float* b0b = (const float*)d_in[5];
    const float* W1a = (const float*)d_in[6];
    const float* b1a = (const float*)d_in[7];
    const float* W1b = (const float*)d_in[8];
    const float* b1b = (const float*)d_in[9];
    float* out = (float*)d_out;

    float* hbuf = nullptr;
    cudaGetSymbolAddress((void**)&hbuf, g_h);

    zero_cnt_kernel<<<1, 32>>>();
    gate_kernel<<<T_TOK / 8, 256>>>(x, Wg);

    dim3 blk(256);
    dim3 gUp(FDIM / 128, T_TOK / 128);   // worst-case M tiles; blocks early-exit on n_e
    dim3 gDn(HDIM / 128, T_TOK / 128);

    // up-projection + activation (GELU for expert 0, ReLU for expert 1)
    gemm_moe_kernel<0><<<gUp, blk>>>(x, W0a, b0a, hbuf, FDIM, HDIM, 0);
    gemm_moe_kernel<1><<<gUp, blk>>>(x, W1a, b1a, hbuf, FDIM, HDIM, 1);
    // down-projection, scatter straight into d_out (every token written exactly once)
    gemm_moe_kernel<2><<<gDn, blk>>>(hbuf, W0b, b0b, out, HDIM, FDIM, 0);
    gemm_moe_kernel<2><<<gDn, blk>>>(hbuf, W1b, b1b, out, HDIM, FDIM, 1);
}

// round 6
// speedup vs baseline: 1.0015x; 1.0015x over previous
#include <cuda_runtime.h>
#include <math.h>

// Problem constants (fixed shapes from reference)
#define T_TOK 8192          // 4 * 2048 tokens
#define HDIM  2048
#define FDIM  4096          // 2*H

// ---------------- scratch (static __device__, allocation-guard safe) -------
__device__ int   g_cnt[2];
__device__ int   g_idx[2][T_TOK];
__device__ float g_h[(size_t)T_TOK * FDIM];   // 134 MB intermediate, indexed by token

// ---------------- packed fp32x2 helpers (full-rate FMA on sm_103a) ---------
typedef unsigned long long u64;

__device__ __forceinline__ u64 fma2(u64 a, u64 b, u64 c) {
    u64 d;
    asm("fma.rn.f32x2 %0, %1, %2, %3;" : "=l"(d) : "l"(a), "l"(b), "l"(c));
    return d;
}
__device__ __forceinline__ u64 pack2(float v) {
    u64 d;
    asm("mov.b64 %0, {%1, %1};" : "=l"(d) : "f"(v));
    return d;
}
__device__ __forceinline__ void unpack2(u64 d, float& lo, float& hi) {
    asm("mov.b64 {%0, %1}, %2;" : "=f"(lo), "=f"(hi) : "l"(d));
}

// ---------------- kernels ---------------------------------------------------

__global__ void zero_cnt_kernel() {
    if (threadIdx.x < 2) g_cnt[threadIdx.x] = 0;
}

// Gate: logits = x @ Wg^T, expert = argmax (softmax is monotone; tie -> 0 like jnp.argmax).
// One warp per token. Compact token ids into per-expert lists.
__global__ void gate_kernel(const float* __restrict__ x, const float* __restrict__ Wg) {
    __shared__ float swg[2 * HDIM];
    int tid = threadIdx.x;
    for (int i = tid; i < 2 * HDIM; i += blockDim.x) swg[i] = Wg[i];
    __syncthreads();

    int warp = tid >> 5, lane = tid & 31;
    int tok = blockIdx.x * 8 + warp;
    const float* xr = x + (size_t)tok * HDIM;

    float a0 = 0.f, a1 = 0.f;
    for (int k = lane; k < HDIM; k += 32) {
        float v = xr[k];
        a0 = fmaf(v, swg[k], a0);
        a1 = fmaf(v, swg[HDIM + k], a1);
    }
#pragma unroll
    for (int o = 16; o; o >>= 1) {
        a0 += __shfl_xor_sync(0xffffffffu, a0, o);
        a1 += __shfl_xor_sync(0xffffffffu, a1, o);
    }
    if (lane == 0) {
        int e = (a1 > a0) ? 1 : 0;            // tie -> expert 0 (argmax-first)
        int pos = atomicAdd(&g_cnt[e], 1);
        g_idx[e][pos] = tok;
    }
}

template <int ACT>
__device__ __forceinline__ float act_fn(float v) {
    if (ACT == 0) return 0.5f * v * (1.0f + erff(v * 0.70710678118654752440f)); // exact GELU
    if (ACT == 1) return fmaxf(v, 0.0f);                                        // ReLU
    return v;
}

// Gathered NT GEMM over one expert's compacted token rows.
//   C[tok, nBase+j] = act( sum_k A[tok,k] * B[nBase+j, k] + bias[nBase+j] )
// A: row-major [*, K] (K contiguous), B: row-major [N, K], tile 128x128x16,
// 256 threads, 8x8 per thread, fp32x2 packed-FMA inner loop.
template <int ACT>
__global__ void __launch_bounds__(256, 2)
gemm_moe_kernel(const float* __restrict__ A,
                const float* __restrict__ B,
                const float* __restrict__ bias,
                float* __restrict__ C, int ldc,
                int K, int expert) {
    const int BM = 128, BN = 128, BK = 16;
    __shared__ __align__(16) float As[BK][BM + 4];
    __shared__ __align__(16) float Bs[BK][BN + 4];
    __shared__ int sTok[BM];

    int n_e = g_cnt[expert];
    int mBase = blockIdx.y * BM;
    if (mBase >= n_e) return;
    int nBase = blockIdx.x * BN;

    int tid = threadIdx.x;
    if (tid < BM) {
        int r = mBase + tid;
        sTok[tid] = (r < n_e) ? g_idx[expert][r] : -1;
    }
    __syncthreads();

    int loadRow  = tid >> 1;
    int loadHalf = (tid & 1) * 4;
    const float* aPtr = nullptr;
    {
        int tokL = sTok[loadRow];
        if (tokL >= 0) aPtr = A + (size_t)tokL * (size_t)K + loadHalf;
    }
    const float* bPtr = B + (size_t)(nBase + loadRow) * (size_t)K + loadHalf;

    int tx = tid & 15, ty = tid >> 4;  // 16 x 16 thread grid

    u64 acc[8][4];                     // [row i][col-pair j] packed fp32x2
#pragma unroll
    for (int i = 0; i < 8; ++i)
#pragma unroll
        for (int j = 0; j < 4; ++j) acc[i][j] = 0ull;

    for (int k0 = 0; k0 < K; k0 += BK) {
        float4 av0 = make_float4(0.f, 0.f, 0.f, 0.f), av1 = av0;
        if (aPtr) {
            av0 = *(const float4*)(aPtr + k0);
            av1 = *(const float4*)(aPtr + k0 + 8);
        }
        float4 bv0 = *(const float4*)(bPtr + k0);
        float4 bv1 = *(const float4*)(bPtr + k0 + 8);

        __syncthreads();
        As[loadHalf + 0][loadRow] = av0.x;
        As[loadHalf + 1][loadRow] = av0.y;
        As[loadHalf + 2][loadRow] = av0.z;
        As[loadHalf + 3][loadRow] = av0.w;
        As[loadHalf + 8][loadRow] = av1.x;
        As[loadHalf + 9][loadRow] = av1.y;
        As[loadHalf + 10][loadRow] = av1.z;
        As[loadHalf + 11][loadRow] = av1.w;
        Bs[loadHalf + 0][loadRow] = bv0.x;
        Bs[loadHalf + 1][loadRow] = bv0.y;
        Bs[loadHalf + 2][loadRow] = bv0.z;
        Bs[loadHalf + 3][loadRow] = bv0.w;
        Bs[loadHalf + 8][loadRow] = bv1.x;
        Bs[loadHalf + 9][loadRow] = bv1.y;
        Bs[loadHalf + 10][loadRow] = bv1.z;
        Bs[loadHalf + 11][loadRow] = bv1.w;
        __syncthreads();

#pragma unroll
        for (int k = 0; k < BK; ++k) {
            float4 a0 = *(const float4*)&As[k][ty * 8];
            float4 a1 = *(const float4*)&As[k][ty * 8 + 4];
            double2 b0 = *(const double2*)&Bs[k][tx * 8];
            double2 b1 = *(const double2*)&Bs[k][tx * 8 + 4];
            u64 bp[4];
            bp[0] = __double_as_longlong(b0.x);
            bp[1] = __double_as_longlong(b0.y);
            bp[2] = __double_as_longlong(b1.x);
            bp[3] = __double_as_longlong(b1.y);
            float aa[8] = {a0.x, a0.y, a0.z, a0.w, a1.x, a1.y, a1.z, a1.w};
#pragma unroll
            for (int i = 0; i < 8; ++i) {
                u64 ai = pack2(aa[i]);
#pragma unroll
                for (int j = 0; j < 4; ++j)
                    acc[i][j] = fma2(ai, bp[j], acc[i][j]);
            }
        }
    }

    // Epilogue: bias + activation, coalesced float4 stores per token row.
    float4 bb0 = *(const float4*)(bias + nBase + tx * 8);
    float4 bb1 = *(const float4*)(bias + nBase + tx * 8 + 4);
    float bvals[8] = {bb0.x, bb0.y, bb0.z, bb0.w, bb1.x, bb1.y, bb1.z, bb1.w};

#pragma unroll
    for (int i = 0; i < 8; ++i) {
        int tok = sTok[ty * 8 + i];
        if (tok < 0) continue;
        float v[8];
#pragma unroll
        for (int j = 0; j < 4; ++j) unpack2(acc[i][j], v[2 * j], v[2 * j + 1]);
#pragma unroll
        for (int c = 0; c < 8; ++c) v[c] = act_fn<ACT>(v[c] + bvals[c]);
        float* cp = C + (size_t)tok * (size_t)ldc + nBase + tx * 8;
        *(float4*)cp       = make_float4(v[0], v[1], v[2], v[3]);
        *(float4*)(cp + 4) = make_float4(v[4], v[5], v[6], v[7]);
    }
}

// ---------------- launch -----------------------------------------------------

extern "C" void kernel_launch(void* const* d_in, const int* in_sizes, int n_in,
                              void* d_out, int out_size) {
    (void)in_sizes; (void)n_in; (void)out_size;
    const float* x   = (const float*)d_in[0];
    const float* Wg  = (const float*)d_in[1];
    const float* W0a = (const float*)d_in[2];
    const float* b0a = (const float*)d_in[3];
    const float* W0b = (const float*)d_in[4];
    const float* b0b = (const float*)d_in[5];
    const float* W1a = (const float*)d_in[6];
    const float* b1a = (const float*)d_in[7];
    const float* W1b = (const float*)d_in[8];
    const float* b1b = (const float*)d_in[9];
    float* out = (float*)d_out;

    float* hbuf = nullptr;
    cudaGetSymbolAddress((void**)&hbuf, g_h);

    zero_cnt_kernel<<<1, 32>>>();
    gate_kernel<<<T_TOK / 8, 256>>>(x, Wg);

    dim3 blk(256);
    dim3 gUp(FDIM / 128, T_TOK / 128);   // worst-case M tiles; blocks early-exit on n_e
    dim3 gDn(HDIM / 128, T_TOK / 128);

    // up-projection + activation (GELU for expert 0, ReLU for expert 1)
    gemm_moe_kernel<0><<<gUp, blk>>>(x, W0a, b0a, hbuf, FDIM, HDIM, 0);
    gemm_moe_kernel<1><<<gUp, blk>>>(x, W1a, b1a, hbuf, FDIM, HDIM, 1);
    // down-projection, scatter straight into d_out (every token written exactly once)
    gemm_moe_kernel<2><<<gDn, blk>>>(hbuf, W0b, b0b, out, HDIM, FDIM, 0);
    gemm_moe_kernel<2><<<gDn, blk>>>(hbuf, W1b, b1b, out, HDIM, FDIM, 1);
}

// round 8
// speedup vs baseline: 3.0197x; 3.0152x over previous
#include <cuda_runtime.h>
#include <cuda_bf16.h>
#include <cstdint>
#include <math.h>

#define T_TOK 8192          // 4 * 2048 tokens
#define HDIM  2048
#define FDIM  4096          // 2*H

// ---------------- static device scratch (no allocs allowed) ----------------
__device__ int g_cnt[2];
__device__ int g_idx[2][T_TOK];
__device__ __nv_bfloat16 g_xh[(size_t)T_TOK * HDIM],  g_xl[(size_t)T_TOK * HDIM];
__device__ __nv_bfloat16 g_w0ah[(size_t)FDIM * HDIM], g_w0al[(size_t)FDIM * HDIM];
__device__ __nv_bfloat16 g_w1ah[(size_t)FDIM * HDIM], g_w1al[(size_t)FDIM * HDIM];
__device__ __nv_bfloat16 g_w0bh[(size_t)HDIM * FDIM], g_w0bl[(size_t)HDIM * FDIM];
__device__ __nv_bfloat16 g_w1bh[(size_t)HDIM * FDIM], g_w1bl[(size_t)HDIM * FDIM];
__device__ __nv_bfloat16 g_hh[(size_t)T_TOK * FDIM],  g_hl[(size_t)T_TOK * FDIM];

// ---------------- PTX helpers (base ISA only — no 'a'-gated features) ------
__device__ __forceinline__ uint32_t smem_u32(const void* p) {
    uint32_t a;
    asm("{ .reg .u64 t; cvta.to.shared.u64 t, %1; cvt.u32.u64 %0, t; }" : "=r"(a) : "l"(p));
    return a;
}
__device__ __forceinline__ void cp16(uint32_t dst, const void* src, uint32_t sz) {
    asm volatile("cp.async.cg.shared.global [%0], [%1], 16, %2;"
                 :: "r"(dst), "l"(src), "r"(sz) : "memory");
}
__device__ __forceinline__ void cp_commit() {
    asm volatile("cp.async.commit_group;" ::: "memory");
}
template <int N>
__device__ __forceinline__ void cp_wait() {
    asm volatile("cp.async.wait_group %0;" :: "n"(N) : "memory");
}
__device__ __forceinline__ void ldm4(uint32_t* r, uint32_t addr) {
    asm volatile("ldmatrix.sync.aligned.m8n8.x4.shared.b16 {%0,%1,%2,%3}, [%4];"
                 : "=r"(r[0]), "=r"(r[1]), "=r"(r[2]), "=r"(r[3]) : "r"(addr));
}
__device__ __forceinline__ void mma16816(float* d, const uint32_t* a, const uint32_t* b) {
    asm volatile(
        "mma.sync.aligned.m16n8k16.row.col.f32.bf16.bf16.f32 "
        "{%0,%1,%2,%3}, {%4,%5,%6,%7}, {%8,%9}, {%0,%1,%2,%3};"
        : "+f"(d[0]), "+f"(d[1]), "+f"(d[2]), "+f"(d[3])
        : "r"(a[0]), "r"(a[1]), "r"(a[2]), "r"(a[3]), "r"(b[0]), "r"(b[1]));
}
__device__ __forceinline__ uint32_t pack_bf(__nv_bfloat16 a, __nv_bfloat16 b) {
    return (uint32_t)__bfloat16_as_ushort(a) | ((uint32_t)__bfloat16_as_ushort(b) << 16);
}

// ---------------- small kernels ---------------------------------------------
__global__ void zero_cnt_kernel() {
    if (threadIdx.x < 2) g_cnt[threadIdx.x] = 0;
}

// Gate: argmax over 2 logits (softmax monotone; tie -> expert 0, jnp.argmax-first).
__global__ void gate_kernel(const float* __restrict__ x, const float* __restrict__ Wg) {
    __shared__ float swg[2 * HDIM];
    int tid = threadIdx.x;
    for (int i = tid; i < 2 * HDIM; i += blockDim.x) swg[i] = Wg[i];
    __syncthreads();
    int warp = tid >> 5, lane = tid & 31;
    int tok = blockIdx.x * 8 + warp;
    const float* xr = x + (size_t)tok * HDIM;
    float a0 = 0.f, a1 = 0.f;
    for (int k = lane; k < HDIM; k += 32) {
        float v = xr[k];
        a0 = fmaf(v, swg[k], a0);
        a1 = fmaf(v, swg[HDIM + k], a1);
    }
#pragma unroll
    for (int o = 16; o; o >>= 1) {
        a0 += __shfl_xor_sync(0xffffffffu, a0, o);
        a1 += __shfl_xor_sync(0xffffffffu, a1, o);
    }
    if (lane == 0) {
        int e = (a1 > a0) ? 1 : 0;
        int pos = atomicAdd(&g_cnt[e], 1);
        g_idx[e][pos] = tok;
    }
}

// fp32 -> (bf16 hi, bf16 lo residual)
__global__ void split_kernel(const float* __restrict__ src,
                             __nv_bfloat16* __restrict__ hi,
                             __nv_bfloat16* __restrict__ lo, int n4) {
    int i = blockIdx.x * blockDim.x + threadIdx.x;
    if (i >= n4) return;
    float4 v = ((const float4*)src)[i];
    __nv_bfloat16 h0 = __float2bfloat16(v.x), h1 = __float2bfloat16(v.y);
    __nv_bfloat16 h2 = __float2bfloat16(v.z), h3 = __float2bfloat16(v.w);
    __nv_bfloat16 l0 = __float2bfloat16(v.x - __bfloat162float(h0));
    __nv_bfloat16 l1 = __float2bfloat16(v.y - __bfloat162float(h1));
    __nv_bfloat16 l2 = __float2bfloat16(v.z - __bfloat162float(h2));
    __nv_bfloat16 l3 = __float2bfloat16(v.w - __bfloat162float(h3));
    ((uint2*)hi)[i] = make_uint2(pack_bf(h0, h1), pack_bf(h2, h3));
    ((uint2*)lo)[i] = make_uint2(pack_bf(l0, l1), pack_bf(l2, l3));
}

template <int ACT>
__device__ __forceinline__ float act_fn(float v) {
    if (ACT == 0) return 0.5f * v * (1.0f + erff(v * 0.70710678118654752440f)); // exact GELU
    if (ACT == 1) return fmaxf(v, 0.0f);                                        // ReLU
    return v;
}

// ---------------- mma.sync gathered GEMM ------------------------------------
// C[tok, n] = act( sum_k A[tok,k]*B[n,k] + bias[n] ),  A rows via g_idx[expert]
// bf16 3-way split: acc += Ah*Bh + Ah*Bl + Al*Bh  (fp32 accum).
// CTA tile 128x128, BK=64, 8 warps (2M x 4N), warp tile 64x32.
// Smem per stage: Ah/Al/Bh/Bl, each 128 rows x 128B, SW128-style swizzle.
static constexpr int GBM = 128, GBN = 128, GBK = 64;
static constexpr uint32_t STAGE_BYTES = 4 * 128 * 128;       // 64 KB
static constexpr uint32_t GEMM_SMEM = 2 * STAGE_BYTES;       // 128 KB dynamic

template <int ACT, bool SPLIT_OUT>
__global__ void __launch_bounds__(256, 1)
gemm_mma(const __nv_bfloat16* __restrict__ Ah, const __nv_bfloat16* __restrict__ Al,
         const __nv_bfloat16* __restrict__ Bh, const __nv_bfloat16* __restrict__ Bl,
         const float* __restrict__ bias,
         float* __restrict__ Cf,
         __nv_bfloat16* __restrict__ Chh, __nv_bfloat16* __restrict__ Chl,
         int K, int ldc, int expert) {
    extern __shared__ char dyn_smem[];
    __shared__ int   sTok[GBM];
    __shared__ float sBias[GBN];

    const int n_e = g_cnt[expert];
    const int mBase = blockIdx.y * GBM;
    if (mBase >= n_e) return;
    const int nBase = blockIdx.x * GBN;
    const uint32_t sb = smem_u32(dyn_smem);
    const int tid = threadIdx.x;

    if (tid < GBM) {
        int r = mBase + tid;
        sTok[tid] = (r < n_e) ? g_idx[expert][r] : -1;
    }
    if (tid < GBN) sBias[tid] = bias[nBase + tid];
    __syncthreads();

    // ---- load-phase thread mapping: 1024 16B-chunks per matrix, 4 per thread
    // chunk idx i: row = i>>3 (0..127), c = i&7 (16B column); swizzled c^(row&7)
    const int nCh = K / GBK;

    auto load_stage = [&](int c, int buf) {
        const int kOff = c * GBK;
        const uint32_t aHs = sb + buf * STAGE_BYTES;
        const uint32_t aLs = aHs + 16384;
        const uint32_t bHs = aHs + 32768;
        const uint32_t bLs = aHs + 49152;
#pragma unroll
        for (int it = 0; it < 4; ++it) {
            int i = tid + it * 256;
            int row = i >> 3, cc = i & 7;
            uint32_t so = (uint32_t)(row * 128 + ((cc ^ (row & 7)) << 4));
            // A (gathered)
            int tok = sTok[row];
            uint32_t sz = (tok >= 0) ? 16u : 0u;
            int tokc = (tok >= 0) ? tok : 0;
            const char* pAh = (const char*)(Ah + (size_t)tokc * K + kOff) + cc * 16;
            const char* pAl = (const char*)(Al + (size_t)tokc * K + kOff) + cc * 16;
            cp16(aHs + so, pAh, sz);
            cp16(aLs + so, pAl, sz);
            // B
            const char* pBh = (const char*)(Bh + (size_t)(nBase + row) * K + kOff) + cc * 16;
            const char* pBl = (const char*)(Bl + (size_t)(nBase + row) * K + kOff) + cc * 16;
            cp16(bHs + so, pBh, 16u);
            cp16(bLs + so, pBl, 16u);
        }
        cp_commit();
    };

    // ---- fragment lane mapping (precomputed row-dependent parts)
    const int lane = tid & 31;
    const int wid = tid >> 5;
    const int wm = wid & 1;       // 0..1  (M)
    const int wn = wid >> 1;      // 0..3  (N)
    // A: lanes 0-15 rows m0+0..15 @k0, lanes 16-31 same rows @k+16B
    const int aRow = lane & 15;
    const int aSel = (lane >> 4) & 1;        // +16B column select
    const int aSw  = aRow & 7;
    // B: row = n0 + (lane&7) + ((lane>>4)&1)*8 ; +16B if (lane>>3)&1
    const int bRow = (lane & 7) + ((lane >> 4) & 1) * 8;
    const int bSel = (lane >> 3) & 1;
    const int bSw  = bRow & 7;

    uint32_t aRowByte[4], bRowByte[2];
#pragma unroll
    for (int mi = 0; mi < 4; ++mi) aRowByte[mi] = (uint32_t)((wm * 64 + mi * 16 + aRow) * 128);
#pragma unroll
    for (int nb = 0; nb < 2; ++nb) bRowByte[nb] = (uint32_t)((wn * 32 + nb * 16 + bRow) * 128);

    float acc[4][4][4];
#pragma unroll
    for (int mi = 0; mi < 4; ++mi)
#pragma unroll
        for (int ni = 0; ni < 4; ++ni)
#pragma unroll
            for (int q = 0; q < 4; ++q) acc[mi][ni][q] = 0.f;

    // ---- pipeline
    load_stage(0, 0);
    for (int c = 0; c < nCh; ++c) {
        int buf = c & 1;
        if (c + 1 < nCh) {
            load_stage(c + 1, buf ^ 1);
            cp_wait<1>();
        } else {
            cp_wait<0>();
        }
        __syncthreads();

        const uint32_t aHs = sb + buf * STAGE_BYTES;
        const uint32_t aLs = aHs + 16384;
        const uint32_t bHs = aHs + 32768;
        const uint32_t bLs = aHs + 49152;

#pragma unroll
        for (int ks = 0; ks < GBK / 16; ++ks) {
            const int kc = ks * 2;  // 16B-chunk base for this kstep
            uint32_t ah[4][4], al[4][4];
            const uint32_t aOff = (uint32_t)(((kc + aSel) ^ aSw) << 4);
#pragma unroll
            for (int mi = 0; mi < 4; ++mi) {
                ldm4(ah[mi], aHs + aRowByte[mi] + aOff);
                ldm4(al[mi], aLs + aRowByte[mi] + aOff);
            }
            uint32_t bh[2][4], bl[2][4];
            const uint32_t bOff = (uint32_t)(((kc + bSel) ^ bSw) << 4);
#pragma unroll
            for (int nb = 0; nb < 2; ++nb) {
                ldm4(bh[nb], bHs + bRowByte[nb] + bOff);
                ldm4(bl[nb], bLs + bRowByte[nb] + bOff);
            }
#pragma unroll
            for (int mi = 0; mi < 4; ++mi)
#pragma unroll
                for (int nb = 0; nb < 2; ++nb)
#pragma unroll
                    for (int h = 0; h < 2; ++h) {
                        float* d = acc[mi][nb * 2 + h];
                        mma16816(d, ah[mi], &bh[nb][h * 2]);
                        mma16816(d, ah[mi], &bl[nb][h * 2]);
                        mma16816(d, al[mi], &bh[nb][h * 2]);
                    }
        }
        __syncthreads();   // buf fully consumed before it is overwritten
    }

    // ---- epilogue: d0,d1 -> (m = lane/4, n = 2*(lane%4)); d2,d3 -> m+8
    const int mrow = lane >> 2;
    const int ncol = 2 * (lane & 3);
#pragma unroll
    for (int mi = 0; mi < 4; ++mi) {
#pragma unroll
        for (int ni = 0; ni < 4; ++ni) {
            int colLoc = wn * 32 + ni * 8 + ncol;
            int col = nBase + colLoc;
            float bv0 = sBias[colLoc], bv1 = sBias[colLoc + 1];
            int rLoc = wm * 64 + mi * 16 + mrow;
            int tok0 = sTok[rLoc], tok1 = sTok[rLoc + 8];
#pragma unroll
            for (int half = 0; half < 2; ++half) {
                int tok = half ? tok1 : tok0;
                if (tok < 0) continue;
                float v0 = act_fn<ACT>(acc[mi][ni][half * 2 + 0] + bv0);
                float v1 = act_fn<ACT>(acc[mi][ni][half * 2 + 1] + bv1);
                size_t base = (size_t)tok * ldc + col;
                if (SPLIT_OUT) {
                    __nv_bfloat16 h0 = __float2bfloat16(v0), h1 = __float2bfloat16(v1);
                    __nv_bfloat16 l0 = __float2bfloat16(v0 - __bfloat162float(h0));
                    __nv_bfloat16 l1 = __float2bfloat16(v1 - __bfloat162float(h1));
                    *(uint32_t*)(Chh + base) = pack_bf(h0, h1);
                    *(uint32_t*)(Chl + base) = pack_bf(l0, l1);
                } else {
                    *(float2*)(Cf + base) = make_float2(v0, v1);
                }
            }
        }
    }
}

// ---------------- launch -----------------------------------------------------
extern "C" void kernel_launch(void* const* d_in, const int* in_sizes, int n_in,
                              void* d_out, int out_size) {
    (void)in_sizes; (void)n_in; (void)out_size;
    const float* x   = (const float*)d_in[0];
    const float* Wg  = (const float*)d_in[1];
    const float* W0a = (const float*)d_in[2];
    const float* b0a = (const float*)d_in[3];
    const float* W0b = (const float*)d_in[4];
    const float* b0b = (const float*)d_in[5];
    const float* W1a = (const float*)d_in[6];
    const float* b1a = (const float*)d_in[7];
    const float* W1b = (const float*)d_in[8];
    const float* b1b = (const float*)d_in[9];
    float* out = (float*)d_out;

    __nv_bfloat16 *xh, *xl, *w0ah, *w0al, *w1ah, *w1al, *w0bh, *w0bl, *w1bh, *w1bl, *hh, *hl;
    cudaGetSymbolAddress((void**)&xh, g_xh);     cudaGetSymbolAddress((void**)&xl, g_xl);
    cudaGetSymbolAddress((void**)&w0ah, g_w0ah); cudaGetSymbolAddress((void**)&w0al, g_w0al);
    cudaGetSymbolAddress((void**)&w1ah, g_w1ah); cudaGetSymbolAddress((void**)&w1al, g_w1al);
    cudaGetSymbolAddress((void**)&w0bh, g_w0bh); cudaGetSymbolAddress((void**)&w0bl, g_w0bl);
    cudaGetSymbolAddress((void**)&w1bh, g_w1bh); cudaGetSymbolAddress((void**)&w1bl, g_w1bl);
    cudaGetSymbolAddress((void**)&hh, g_hh);     cudaGetSymbolAddress((void**)&hl, g_hl);

    cudaFuncSetAttribute(gemm_mma<0, true>,  cudaFuncAttributeMaxDynamicSharedMemorySize, GEMM_SMEM);
    cudaFuncSetAttribute(gemm_mma<1, true>,  cudaFuncAttributeMaxDynamicSharedMemorySize, GEMM_SMEM);
    cudaFuncSetAttribute(gemm_mma<2, false>, cudaFuncAttributeMaxDynamicSharedMemorySize, GEMM_SMEM);

    zero_cnt_kernel<<<1, 32>>>();
    gate_kernel<<<T_TOK / 8, 256>>>(x, Wg);

    // fp32 -> bf16 hi/lo splits
    {
        int n4 = T_TOK * HDIM / 4;
        split_kernel<<<n4 / 256, 256>>>(x, xh, xl, n4);
        n4 = FDIM * HDIM / 4;
        split_kernel<<<n4 / 256, 256>>>(W0a, w0ah, w0al, n4);
        split_kernel<<<n4 / 256, 256>>>(W1a, w1ah, w1al, n4);
        split_kernel<<<n4 / 256, 256>>>(W0b, w0bh, w0bl, n4);
        split_kernel<<<n4 / 256, 256>>>(W1b, w1bh, w1bl, n4);
    }

    dim3 blk(256);
    dim3 gUp(FDIM / GBN, T_TOK / GBM);   // (32, 64), blocks early-exit on n_e
    dim3 gDn(HDIM / GBN, T_TOK / GBM);   // (16, 64)

    // up-projection + activation -> h (bf16 hi/lo)
    gemm_mma<0, true><<<gUp, blk, GEMM_SMEM>>>(xh, xl, w0ah, w0al, b0a,
                                               nullptr, hh, hl, HDIM, FDIM, 0);
    gemm_mma<1, true><<<gUp, blk, GEMM_SMEM>>>(xh, xl, w1ah, w1al, b1a,
                                               nullptr, hh, hl, HDIM, FDIM, 1);
    // down-projection -> out (fp32), each token written exactly once
    gemm_mma<2, false><<<gDn, blk, GEMM_SMEM>>>(hh, hl, w0bh, w0bl, b0b,
                                                out, nullptr, nullptr, FDIM, HDIM, 0);
    gemm_mma<2, false><<<gDn, blk, GEMM_SMEM>>>(hh, hl, w1bh, w1bl, b1b,
                                                out, nullptr, nullptr, FDIM, HDIM, 1);
}

// round 9
// speedup vs baseline: 4.7158x; 1.5617x over previous
#include <cuda_runtime.h>
#include <cuda_fp16.h>
#include <cstdint>
#include <math.h>

#define T_TOK 8192          // 4 * 2048 tokens
#define HDIM  2048
#define FDIM  4096          // 2*H

// ---------------- static device scratch (no allocs allowed) ----------------
__device__ int g_cnt[2];
__device__ int g_idx[2][T_TOK];
__device__ __half g_xh[(size_t)T_TOK * HDIM], g_xl[(size_t)T_TOK * HDIM];
__device__ __half g_w0a[(size_t)FDIM * HDIM], g_w1a[(size_t)FDIM * HDIM];
__device__ __half g_w0b[(size_t)HDIM * FDIM], g_w1b[(size_t)HDIM * FDIM];
__device__ __half g_hh[(size_t)T_TOK * FDIM], g_hl[(size_t)T_TOK * FDIM];

// ---------------- PTX helpers (base ISA only — no 'a'-gated features) ------
__device__ __forceinline__ uint32_t smem_u32(const void* p) {
    uint32_t a;
    asm("{ .reg .u64 t; cvta.to.shared.u64 t, %1; cvt.u32.u64 %0, t; }" : "=r"(a) : "l"(p));
    return a;
}
__device__ __forceinline__ void cp16(uint32_t dst, const void* src, uint32_t sz) {
    asm volatile("cp.async.cg.shared.global [%0], [%1], 16, %2;"
                 :: "r"(dst), "l"(src), "r"(sz) : "memory");
}
__device__ __forceinline__ void cp_commit() {
    asm volatile("cp.async.commit_group;" ::: "memory");
}
template <int N>
__device__ __forceinline__ void cp_wait() {
    asm volatile("cp.async.wait_group %0;" :: "n"(N) : "memory");
}
__device__ __forceinline__ void ldm4(uint32_t* r, uint32_t addr) {
    asm volatile("ldmatrix.sync.aligned.m8n8.x4.shared.b16 {%0,%1,%2,%3}, [%4];"
                 : "=r"(r[0]), "=r"(r[1]), "=r"(r[2]), "=r"(r[3]) : "r"(addr));
}
__device__ __forceinline__ void mma16816(float* d, const uint32_t* a, const uint32_t* b) {
    asm volatile(
        "mma.sync.aligned.m16n8k16.row.col.f32.f16.f16.f32 "
        "{%0,%1,%2,%3}, {%4,%5,%6,%7}, {%8,%9}, {%0,%1,%2,%3};"
        : "+f"(d[0]), "+f"(d[1]), "+f"(d[2]), "+f"(d[3])
        : "r"(a[0]), "r"(a[1]), "r"(a[2]), "r"(a[3]), "r"(b[0]), "r"(b[1]));
}
__device__ __forceinline__ uint32_t pack_h(__half a, __half b) {
    return (uint32_t)__half_as_ushort(a) | ((uint32_t)__half_as_ushort(b) << 16);
}

// ---------------- small kernels ---------------------------------------------
__global__ void zero_cnt_kernel() {
    if (threadIdx.x < 2) g_cnt[threadIdx.x] = 0;
}

// Gate: argmax over 2 logits (softmax monotone; tie -> expert 0, jnp.argmax-first).
__global__ void gate_kernel(const float* __restrict__ x, const float* __restrict__ Wg) {
    __shared__ float swg[2 * HDIM];
    int tid = threadIdx.x;
    for (int i = tid; i < 2 * HDIM; i += blockDim.x) swg[i] = Wg[i];
    __syncthreads();
    int warp = tid >> 5, lane = tid & 31;
    int tok = blockIdx.x * 8 + warp;
    const float* xr = x + (size_t)tok * HDIM;
    float a0 = 0.f, a1 = 0.f;
    for (int k = lane; k < HDIM; k += 32) {
        float v = xr[k];
        a0 = fmaf(v, swg[k], a0);
        a1 = fmaf(v, swg[HDIM + k], a1);
    }
#pragma unroll
    for (int o = 16; o; o >>= 1) {
        a0 += __shfl_xor_sync(0xffffffffu, a0, o);
        a1 += __shfl_xor_sync(0xffffffffu, a1, o);
    }
    if (lane == 0) {
        int e = (a1 > a0) ? 1 : 0;
        int pos = atomicAdd(&g_cnt[e], 1);
        g_idx[e][pos] = tok;
    }
}

// fp32 -> (fp16 hi, fp16 lo residual)
__global__ void split_hl_kernel(const float* __restrict__ src,
                                __half* __restrict__ hi,
                                __half* __restrict__ lo, int n4) {
    int i = blockIdx.x * blockDim.x + threadIdx.x;
    if (i >= n4) return;
    float4 v = ((const float4*)src)[i];
    __half h0 = __float2half(v.x), h1 = __float2half(v.y);
    __half h2 = __float2half(v.z), h3 = __float2half(v.w);
    __half l0 = __float2half(v.x - __half2float(h0));
    __half l1 = __float2half(v.y - __half2float(h1));
    __half l2 = __float2half(v.z - __half2float(h2));
    __half l3 = __float2half(v.w - __half2float(h3));
    ((uint2*)hi)[i] = make_uint2(pack_h(h0, h1), pack_h(h2, h3));
    ((uint2*)lo)[i] = make_uint2(pack_h(l0, l1), pack_h(l2, l3));
}

// fp32 -> fp16 (hi only, for weights)
__global__ void split_h_kernel(const float* __restrict__ src,
                               __half* __restrict__ hi, int n4) {
    int i = blockIdx.x * blockDim.x + threadIdx.x;
    if (i >= n4) return;
    float4 v = ((const float4*)src)[i];
    ((uint2*)hi)[i] = make_uint2(pack_h(__float2half(v.x), __float2half(v.y)),
                                 pack_h(__float2half(v.z), __float2half(v.w)));
}

template <int ACT>
__device__ __forceinline__ float act_fn(float v) {
    if (ACT == 0) return 0.5f * v * (1.0f + erff(v * 0.70710678118654752440f)); // exact GELU
    if (ACT == 1) return fmaxf(v, 0.0f);                                        // ReLU
    return v;
}

// ---------------- mma.sync gathered GEMM ------------------------------------
// C[tok, n] = act( sum_k A[tok,k]*B[n,k] + bias[n] ),  A rows via g_idx[expert]
// fp16 2-term split: acc += Ah*B + Al*B  (A exact to ~2^-22, B = fp16(W)).
// CTA tile 128x128, BK=64, 8 warps (2M x 4N), warp tile 64x32.
// Smem per stage: Ah/Al/B, each 128 rows x 128B, XOR-swizzled; 2 stages, 2 CTA/SM.
static constexpr int GBM = 128, GBN = 128, GBK = 64;
static constexpr uint32_t STAGE_BYTES = 3 * 128 * 128;       // 48 KB
static constexpr uint32_t GEMM_SMEM = 2 * STAGE_BYTES;       // 96 KB dynamic

template <int ACT, bool SPLIT_OUT>
__global__ void __launch_bounds__(256, 2)
gemm_mma(const __half* __restrict__ Ah, const __half* __restrict__ Al,
         const __half* __restrict__ B,
         const float* __restrict__ bias,
         float* __restrict__ Cf,
         __half* __restrict__ Chh, __half* __restrict__ Chl,
         int K, int ldc, int expert) {
    extern __shared__ char dyn_smem[];
    __shared__ int   sTok[GBM];
    __shared__ float sBias[GBN];

    const int n_e = g_cnt[expert];
    const int mBase = blockIdx.y * GBM;
    if (mBase >= n_e) return;
    const int nBase = blockIdx.x * GBN;
    const uint32_t sb = smem_u32(dyn_smem);
    const int tid = threadIdx.x;

    if (tid < GBM) {
        int r = mBase + tid;
        sTok[tid] = (r < n_e) ? g_idx[expert][r] : -1;
    }
    if (tid < GBN) sBias[tid] = bias[nBase + tid];
    __syncthreads();

    const int nCh = K / GBK;

    // 1024 16B-chunks per matrix; row = i>>3, c = i&7, swizzle c^(row&7)
    auto load_stage = [&](int c, int buf) {
        const int kOff = c * GBK;
        const uint32_t aHs = sb + buf * STAGE_BYTES;
        const uint32_t aLs = aHs + 16384;
        const uint32_t bS  = aHs + 32768;
#pragma unroll
        for (int it = 0; it < 4; ++it) {
            int i = tid + it * 256;
            int row = i >> 3, cc = i & 7;
            uint32_t so = (uint32_t)(row * 128 + ((cc ^ (row & 7)) << 4));
            int tok = sTok[row];
            uint32_t sz = (tok >= 0) ? 16u : 0u;
            int tokc = (tok >= 0) ? tok : 0;
            const char* pAh = (const char*)(Ah + (size_t)tokc * K + kOff) + cc * 16;
            const char* pAl = (const char*)(Al + (size_t)tokc * K + kOff) + cc * 16;
            cp16(aHs + so, pAh, sz);
            cp16(aLs + so, pAl, sz);
            const char* pB = (const char*)(B + (size_t)(nBase + row) * K + kOff) + cc * 16;
            cp16(bS + so, pB, 16u);
        }
        cp_commit();
    };

    // fragment lane mapping
    const int lane = tid & 31;
    const int wid = tid >> 5;
    const int wm = wid & 1;       // M
    const int wn = wid >> 1;      // N
    const int aRow = lane & 15;
    const int aSel = (lane >> 4) & 1;
    const int aSw  = aRow & 7;
    const int bRow = (lane & 7) + ((lane >> 4) & 1) * 8;
    const int bSel = (lane >> 3) & 1;
    const int bSw  = bRow & 7;

    uint32_t aRowByte[4], bRowByte[2];
#pragma unroll
    for (int mi = 0; mi < 4; ++mi) aRowByte[mi] = (uint32_t)((wm * 64 + mi * 16 + aRow) * 128);
#pragma unroll
    for (int nb = 0; nb < 2; ++nb) bRowByte[nb] = (uint32_t)((wn * 32 + nb * 16 + bRow) * 128);

    float acc[4][4][4];
#pragma unroll
    for (int mi = 0; mi < 4; ++mi)
#pragma unroll
        for (int ni = 0; ni < 4; ++ni)
#pragma unroll
            for (int q = 0; q < 4; ++q) acc[mi][ni][q] = 0.f;

    load_stage(0, 0);
    for (int c = 0; c < nCh; ++c) {
        int buf = c & 1;
        if (c + 1 < nCh) {
            load_stage(c + 1, buf ^ 1);
            cp_wait<1>();
        } else {
            cp_wait<0>();
        }
        __syncthreads();

        const uint32_t aHs = sb + buf * STAGE_BYTES;
        const uint32_t aLs = aHs + 16384;
        const uint32_t bS  = aHs + 32768;

#pragma unroll
        for (int ks = 0; ks < GBK / 16; ++ks) {
            const int kc = ks * 2;
            const uint32_t aOff = (uint32_t)(((kc + aSel) ^ aSw) << 4);
            const uint32_t bOff = (uint32_t)(((kc + bSel) ^ bSw) << 4);
            uint32_t bh[2][4];
#pragma unroll
            for (int nb = 0; nb < 2; ++nb) ldm4(bh[nb], bS + bRowByte[nb] + bOff);
#pragma unroll
            for (int mi = 0; mi < 4; ++mi) {
                uint32_t af[4];
                ldm4(af, aHs + aRowByte[mi] + aOff);
#pragma unroll
                for (int nb = 0; nb < 2; ++nb)
#pragma unroll
                    for (int h = 0; h < 2; ++h)
                        mma16816(acc[mi][nb * 2 + h], af, &bh[nb][h * 2]);
                ldm4(af, aLs + aRowByte[mi] + aOff);
#pragma unroll
                for (int nb = 0; nb < 2; ++nb)
#pragma unroll
                    for (int h = 0; h < 2; ++h)
                        mma16816(acc[mi][nb * 2 + h], af, &bh[nb][h * 2]);
            }
        }
        __syncthreads();
    }

    // epilogue: d0,d1 -> (m = lane/4, n = 2*(lane%4)); d2,d3 -> m+8
    const int mrow = lane >> 2;
    const int ncol = 2 * (lane & 3);
#pragma unroll
    for (int mi = 0; mi < 4; ++mi) {
#pragma unroll
        for (int ni = 0; ni < 4; ++ni) {
            int colLoc = wn * 32 + ni * 8 + ncol;
            int col = nBase + colLoc;
            float bv0 = sBias[colLoc], bv1 = sBias[colLoc + 1];
            int rLoc = wm * 64 + mi * 16 + mrow;
            int tok0 = sTok[rLoc], tok1 = sTok[rLoc + 8];
#pragma unroll
            for (int half = 0; half < 2; ++half) {
                int tok = half ? tok1 : tok0;
                if (tok < 0) continue;
                float v0 = act_fn<ACT>(acc[mi][ni][half * 2 + 0] + bv0);
                float v1 = act_fn<ACT>(acc[mi][ni][half * 2 + 1] + bv1);
                size_t base = (size_t)tok * ldc + col;
                if (SPLIT_OUT) {
                    __half h0 = __float2half(v0), h1 = __float2half(v1);
                    __half l0 = __float2half(v0 - __half2float(h0));
                    __half l1 = __float2half(v1 - __half2float(h1));
                    *(uint32_t*)(Chh + base) = pack_h(h0, h1);
                    *(uint32_t*)(Chl + base) = pack_h(l0, l1);
                } else {
                    *(float2*)(Cf + base) = make_float2(v0, v1);
                }
            }
        }
    }
}

// ---------------- launch -----------------------------------------------------
extern "C" void kernel_launch(void* const* d_in, const int* in_sizes, int n_in,
                              void* d_out, int out_size) {
    (void)in_sizes; (void)n_in; (void)out_size;
    const float* x   = (const float*)d_in[0];
    const float* Wg  = (const float*)d_in[1];
    const float* W0a = (const float*)d_in[2];
    const float* b0a = (const float*)d_in[3];
    const float* W0b = (const float*)d_in[4];
    const float* b0b = (const float*)d_in[5];
    const float* W1a = (const float*)d_in[6];
    const float* b1a = (const float*)d_in[7];
    const float* W1b = (const float*)d_in[8];
    const float* b1b = (const float*)d_in[9];
    float* out = (float*)d_out;

    __half *xh, *xl, *w0a, *w1a, *w0b, *w1b, *hh, *hl;
    cudaGetSymbolAddress((void**)&xh, g_xh);   cudaGetSymbolAddress((void**)&xl, g_xl);
    cudaGetSymbolAddress((void**)&w0a, g_w0a); cudaGetSymbolAddress((void**)&w1a, g_w1a);
    cudaGetSymbolAddress((void**)&w0b, g_w0b); cudaGetSymbolAddress((void**)&w1b, g_w1b);
    cudaGetSymbolAddress((void**)&hh, g_hh);   cudaGetSymbolAddress((void**)&hl, g_hl);

    cudaFuncSetAttribute(gemm_mma<0, true>,  cudaFuncAttributeMaxDynamicSharedMemorySize, GEMM_SMEM);
    cudaFuncSetAttribute(gemm_mma<1, true>,  cudaFuncAttributeMaxDynamicSharedMemorySize, GEMM_SMEM);
    cudaFuncSetAttribute(gemm_mma<2, false>, cudaFuncAttributeMaxDynamicSharedMemorySize, GEMM_SMEM);

    zero_cnt_kernel<<<1, 32>>>();
    gate_kernel<<<T_TOK / 8, 256>>>(x, Wg);

    {
        int n4 = T_TOK * HDIM / 4;
        split_hl_kernel<<<n4 / 256, 256>>>(x, xh, xl, n4);
        n4 = FDIM * HDIM / 4;
        split_h_kernel<<<n4 / 256, 256>>>(W0a, w0a, n4);
        split_h_kernel<<<n4 / 256, 256>>>(W1a, w1a, n4);
        split_h_kernel<<<n4 / 256, 256>>>(W0b, w0b, n4);
        split_h_kernel<<<n4 / 256, 256>>>(W1b, w1b, n4);
    }

    dim3 blk(256);
    dim3 gUp(FDIM / GBN, T_TOK / GBM);   // (32, 64), blocks early-exit on n_e
    dim3 gDn(HDIM / GBN, T_TOK / GBM);   // (16, 64)

    // up-projection + activation -> h (fp16 hi/lo)
    gemm_mma<0, true><<<gUp, blk, GEMM_SMEM>>>(xh, xl, w0a, b0a,
                                               nullptr, hh, hl, HDIM, FDIM, 0);
    gemm_mma<1, true><<<gUp, blk, GEMM_SMEM>>>(xh, xl, w1a, b1a,
                                               nullptr, hh, hl, HDIM, FDIM, 1);
    // down-projection -> out (fp32), each token written exactly once
    gemm_mma<2, false><<<gDn, blk, GEMM_SMEM>>>(hh, hl, w0b, b0b,
                                                out, nullptr, nullptr, FDIM, HDIM, 0);
    gemm_mma<2, false><<<gDn, blk, GEMM_SMEM>>>(hh, hl, w1b, b1b,
                                                out, nullptr, nullptr, FDIM, HDIM, 1);
}

// round 10
// speedup vs baseline: 5.1472x; 1.0915x over previous
#include <cuda_runtime.h>
#include <cuda_fp16.h>
#include <cstdint>
#include <math.h>

#define T_TOK 8192          // 4 * 2048 tokens
#define HDIM  2048
#define FDIM  4096          // 2*H

// ---------------- static device scratch (no allocs allowed) ----------------
__device__ int g_cnt[2];
__device__ int g_idx[2][T_TOK];
__device__ __half g_xh[(size_t)T_TOK * HDIM], g_xl[(size_t)T_TOK * HDIM];
__device__ __half g_w0a[(size_t)FDIM * HDIM], g_w1a[(size_t)FDIM * HDIM];
__device__ __half g_w0b[(size_t)HDIM * FDIM], g_w1b[(size_t)HDIM * FDIM];
__device__ __half g_hh[(size_t)T_TOK * FDIM], g_hl[(size_t)T_TOK * FDIM];

// ---------------- PTX helpers (base ISA only — no 'a'-gated features) ------
__device__ __forceinline__ uint32_t smem_u32(const void* p) {
    uint32_t a;
    asm("{ .reg .u64 t; cvta.to.shared.u64 t, %1; cvt.u32.u64 %0, t; }" : "=r"(a) : "l"(p));
    return a;
}
__device__ __forceinline__ void cp16(uint32_t dst, const void* src, uint32_t sz) {
    asm volatile("cp.async.cg.shared.global [%0], [%1], 16, %2;"
                 :: "r"(dst), "l"(src), "r"(sz) : "memory");
}
__device__ __forceinline__ void cp_commit() {
    asm volatile("cp.async.commit_group;" ::: "memory");
}
template <int N>
__device__ __forceinline__ void cp_wait() {
    asm volatile("cp.async.wait_group %0;" :: "n"(N) : "memory");
}
__device__ __forceinline__ void ldm4(uint32_t* r, uint32_t addr) {
    asm volatile("ldmatrix.sync.aligned.m8n8.x4.shared.b16 {%0,%1,%2,%3}, [%4];"
                 : "=r"(r[0]), "=r"(r[1]), "=r"(r[2]), "=r"(r[3]) : "r"(addr));
}
__device__ __forceinline__ void mma16816(float* d, const uint32_t* a, const uint32_t* b) {
    asm volatile(
        "mma.sync.aligned.m16n8k16.row.col.f32.f16.f16.f32 "
        "{%0,%1,%2,%3}, {%4,%5,%6,%7}, {%8,%9}, {%0,%1,%2,%3};"
        : "+f"(d[0]), "+f"(d[1]), "+f"(d[2]), "+f"(d[3])
        : "r"(a[0]), "r"(a[1]), "r"(a[2]), "r"(a[3]), "r"(b[0]), "r"(b[1]));
}
__device__ __forceinline__ uint32_t pack_h(__half a, __half b) {
    return (uint32_t)__half_as_ushort(a) | ((uint32_t)__half_as_ushort(b) << 16);
}

// ---------------- small kernels ---------------------------------------------
__global__ void zero_cnt_kernel() {
    if (threadIdx.x < 2) g_cnt[threadIdx.x] = 0;
}

// Fused gate + x hi/lo split. One warp per token: single pass over x computes
// both gate logits AND writes fp16 hi/lo splits. argmax over 2 logits
// (softmax monotone; tie -> expert 0, matching jnp.argmax-first).
__global__ void gate_split_kernel(const float* __restrict__ x,
                                  const float* __restrict__ Wg,
                                  __half* __restrict__ xh,
                                  __half* __restrict__ xl) {
    __shared__ float swg[2 * HDIM];
    int tid = threadIdx.x;
    for (int i = tid; i < 2 * HDIM; i += blockDim.x) swg[i] = Wg[i];
    __syncthreads();
    int warp = tid >> 5, lane = tid & 31;
    int tok = blockIdx.x * 8 + warp;
    size_t rowOff = (size_t)tok * HDIM;
    const float4* xr = (const float4*)(x + rowOff);
    uint2* hh = (uint2*)(xh + rowOff);
    uint2* hl = (uint2*)(xl + rowOff);

    float a0 = 0.f, a1 = 0.f;
#pragma unroll
    for (int j = 0; j < HDIM / 128; ++j) {        // 16 iters of float4 per lane
        int i4 = lane + 32 * j;                   // float4 index within row
        float4 v = xr[i4];
        int k = i4 * 4;
        a0 = fmaf(v.x, swg[k], fmaf(v.y, swg[k + 1], fmaf(v.z, swg[k + 2], fmaf(v.w, swg[k + 3], a0))));
        a1 = fmaf(v.x, swg[HDIM + k], fmaf(v.y, swg[HDIM + k + 1],
             fmaf(v.z, swg[HDIM + k + 2], fmaf(v.w, swg[HDIM + k + 3], a1))));
        __half h0 = __float2half(v.x), h1 = __float2half(v.y);
        __half h2 = __float2half(v.z), h3 = __float2half(v.w);
        __half l0 = __float2half(v.x - __half2float(h0));
        __half l1 = __float2half(v.y - __half2float(h1));
        __half l2 = __float2half(v.z - __half2float(h2));
        __half l3 = __float2half(v.w - __half2float(h3));
        hh[i4] = make_uint2(pack_h(h0, h1), pack_h(h2, h3));
        hl[i4] = make_uint2(pack_h(l0, l1), pack_h(l2, l3));
    }
#pragma unroll
    for (int o = 16; o; o >>= 1) {
        a0 += __shfl_xor_sync(0xffffffffu, a0, o);
        a1 += __shfl_xor_sync(0xffffffffu, a1, o);
    }
    if (lane == 0) {
        int e = (a1 > a0) ? 1 : 0;
        int pos = atomicAdd(&g_cnt[e], 1);
        g_idx[e][pos] = tok;
    }
}

// fp32 -> fp16 weight convert; blockIdx.z selects which of two tensors.
__global__ void splitW_kernel(const float* __restrict__ s0, __half* __restrict__ d0,
                              const float* __restrict__ s1, __half* __restrict__ d1,
                              int n4) {
    int i = blockIdx.x * blockDim.x + threadIdx.x;
    if (i >= n4) return;
    const float* src = blockIdx.z ? s1 : s0;
    __half* dst = blockIdx.z ? d1 : d0;
    float4 v = ((const float4*)src)[i];
    ((uint2*)dst)[i] = make_uint2(pack_h(__float2half(v.x), __float2half(v.y)),
                                  pack_h(__float2half(v.z), __float2half(v.w)));
}

template <int ACT>
__device__ __forceinline__ float act_fn(float v) {
    if (ACT == 0) return 0.5f * v * (1.0f + erff(v * 0.70710678118654752440f)); // exact GELU
    if (ACT == 1) return fmaxf(v, 0.0f);                                        // ReLU
    return v;
}

// ---------------- mma.sync gathered GEMM ------------------------------------
// C[tok, n] = act_e( sum_k A[tok,k]*B_e[n,k] + bias_e[n] ), e = blockIdx.z,
// A rows via g_idx[e]. fp16 2-term split: acc += Ah*B + Al*B.
// CTA tile 128x128, BK=64, 8 warps (2M x 4N), warp tile 64x32.
// Smem per stage: Ah/Al/B, 128 rows x 128B each, XOR-swizzled; 2 stages, 2 CTA/SM.
static constexpr int GBM = 128, GBN = 128, GBK = 64;
static constexpr uint32_t STAGE_BYTES = 3 * 128 * 128;       // 48 KB
static constexpr uint32_t GEMM_SMEM = 2 * STAGE_BYTES;       // 96 KB dynamic

// ACT0/ACT1: activation for expert0/expert1 (up: GELU/ReLU; down: none/none)
template <int ACT0, int ACT1, bool SPLIT_OUT>
__global__ void __launch_bounds__(256, 2)
gemm_mma(const __half* __restrict__ Ah, const __half* __restrict__ Al,
         const __half* __restrict__ B0, const __half* __restrict__ B1,
         const float* __restrict__ bias0, const float* __restrict__ bias1,
         float* __restrict__ Cf,
         __half* __restrict__ Chh, __half* __restrict__ Chl,
         int K, int ldc) {
    extern __shared__ char dyn_smem[];
    __shared__ int   sTok[GBM];
    __shared__ float sBias[GBN];

    const int expert = blockIdx.z;
    const int n_e = g_cnt[expert];
    const int mBase = blockIdx.y * GBM;
    if (mBase >= n_e) return;
    const int nBase = blockIdx.x * GBN;
    const __half* B = expert ? B1 : B0;
    const float* bias = expert ? bias1 : bias0;
    const uint32_t sb = smem_u32(dyn_smem);
    const int tid = threadIdx.x;

    if (tid < GBM) {
        int r = mBase + tid;
        sTok[tid] = (r < n_e) ? g_idx[expert][r] : -1;
    }
    if (tid < GBN) sBias[tid] = bias[nBase + tid];
    __syncthreads();

    const int nCh = K / GBK;

    // 1024 16B-chunks per matrix; row = i>>3, c = i&7, swizzle c^(row&7)
    auto load_stage = [&](int c, int buf) {
        const int kOff = c * GBK;
        const uint32_t aHs = sb + buf * STAGE_BYTES;
        const uint32_t aLs = aHs + 16384;
        const uint32_t bS  = aHs + 32768;
#pragma unroll
        for (int it = 0; it < 4; ++it) {
            int i = tid + it * 256;
            int row = i >> 3, cc = i & 7;
            uint32_t so = (uint32_t)(row * 128 + ((cc ^ (row & 7)) << 4));
            int tok = sTok[row];
            uint32_t sz = (tok >= 0) ? 16u : 0u;
            int tokc = (tok >= 0) ? tok : 0;
            const char* pAh = (const char*)(Ah + (size_t)tokc * K + kOff) + cc * 16;
            const char* pAl = (const char*)(Al + (size_t)tokc * K + kOff) + cc * 16;
            cp16(aHs + so, pAh, sz);
            cp16(aLs + so, pAl, sz);
            const char* pB = (const char*)(B + (size_t)(nBase + row) * K + kOff) + cc * 16;
            cp16(bS + so, pB, 16u);
        }
        cp_commit();
    };

    // fragment lane mapping
    const int lane = tid & 31;
    const int wid = tid >> 5;
    const int wm = wid & 1;       // M
    const int wn = wid >> 1;      // N
    const int aRow = lane & 15;
    const int aSel = (lane >> 4) & 1;
    const int aSw  = aRow & 7;
    const int bRow = (lane & 7) + ((lane >> 4) & 1) * 8;
    const int bSel = (lane >> 3) & 1;
    const int bSw  = bRow & 7;

    uint32_t aRowByte[4], bRowByte[2];
#pragma unroll
    for (int mi = 0; mi < 4; ++mi) aRowByte[mi] = (uint32_t)((wm * 64 + mi * 16 + aRow) * 128);
#pragma unroll
    for (int nb = 0; nb < 2; ++nb) bRowByte[nb] = (uint32_t)((wn * 32 + nb * 16 + bRow) * 128);

    float acc[4][4][4];
#pragma unroll
    for (int mi = 0; mi < 4; ++mi)
#pragma unroll
        for (int ni = 0; ni < 4; ++ni)
#pragma unroll
            for (int q = 0; q < 4; ++q) acc[mi][ni][q] = 0.f;

    load_stage(0, 0);
    for (int c = 0; c < nCh; ++c) {
        int buf = c & 1;
        if (c + 1 < nCh) {
            load_stage(c + 1, buf ^ 1);
            cp_wait<1>();
        } else {
            cp_wait<0>();
        }
        __syncthreads();

        const uint32_t aHs = sb + buf * STAGE_BYTES;
        const uint32_t aLs = aHs + 16384;
        const uint32_t bS  = aHs + 32768;

#pragma unroll
        for (int ks = 0; ks < GBK / 16; ++ks) {
            const int kc = ks * 2;
            const uint32_t aOff = (uint32_t)(((kc + aSel) ^ aSw) << 4);
            const uint32_t bOff = (uint32_t)(((kc + bSel) ^ bSw) << 4);
            uint32_t bh[2][4];
#pragma unroll
            for (int nb = 0; nb < 2; ++nb) ldm4(bh[nb], bS + bRowByte[nb] + bOff);
#pragma unroll
            for (int mi = 0; mi < 4; ++mi) {
                uint32_t af[4];
                ldm4(af, aHs + aRowByte[mi] + aOff);
#pragma unroll
                for (int nb = 0; nb < 2; ++nb)
#pragma unroll
                    for (int h = 0; h < 2; ++h)
                        mma16816(acc[mi][nb * 2 + h], af, &bh[nb][h * 2]);
                ldm4(af, aLs + aRowByte[mi] + aOff);
#pragma unroll
                for (int nb = 0; nb < 2; ++nb)
#pragma unroll
                    for (int h = 0; h < 2; ++h)
                        mma16816(acc[mi][nb * 2 + h], af, &bh[nb][h * 2]);
            }
        }
        __syncthreads();
    }

    // epilogue: d0,d1 -> (m = lane/4, n = 2*(lane%4)); d2,d3 -> m+8
    const int mrow = lane >> 2;
    const int ncol = 2 * (lane & 3);
#pragma unroll
    for (int mi = 0; mi < 4; ++mi) {
#pragma unroll
        for (int ni = 0; ni < 4; ++ni) {
            int colLoc = wn * 32 + ni * 8 + ncol;
            int col = nBase + colLoc;
            float bv0 = sBias[colLoc], bv1 = sBias[colLoc + 1];
            int rLoc = wm * 64 + mi * 16 + mrow;
            int tok0 = sTok[rLoc], tok1 = sTok[rLoc + 8];
#pragma unroll
            for (int half = 0; half < 2; ++half) {
                int tok = half ? tok1 : tok0;
                if (tok < 0) continue;
                float r0 = acc[mi][ni][half * 2 + 0] + bv0;
                float r1 = acc[mi][ni][half * 2 + 1] + bv1;
                float v0 = expert ? act_fn<ACT1>(r0) : act_fn<ACT0>(r0);
                float v1 = expert ? act_fn<ACT1>(r1) : act_fn<ACT0>(r1);
                size_t base = (size_t)tok * ldc + col;
                if (SPLIT_OUT) {
                    __half h0 = __float2half(v0), h1 = __float2half(v1);
                    __half l0 = __float2half(v0 - __half2float(h0));
                    __half l1 = __float2half(v1 - __half2float(h1));
                    *(uint32_t*)(Chh + base) = pack_h(h0, h1);
                    *(uint32_t*)(Chl + base) = pack_h(l0, l1);
                } else {
                    *(float2*)(Cf + base) = make_float2(v0, v1);
                }
            }
        }
    }
}

// ---------------- launch -----------------------------------------------------
extern "C" void kernel_launch(void* const* d_in, const int* in_sizes, int n_in,
                              void* d_out, int out_size) {
    (void)in_sizes; (void)n_in; (void)out_size;
    const float* x   = (const float*)d_in[0];
    const float* Wg  = (const float*)d_in[1];
    const float* W0a = (const float*)d_in[2];
    const float* b0a = (const float*)d_in[3];
    const float* W0b = (const float*)d_in[4];
    const float* b0b = (const float*)d_in[5];
    const float* W1a = (const float*)d_in[6];
    const float* b1a = (const float*)d_in[7];
    const float* W1b = (const float*)d_in[8];
    const float* b1b = (const float*)d_in[9];
    float* out = (float*)d_out;

    __half *xh, *xl, *w0a, *w1a, *w0b, *w1b, *hh, *hl;
    cudaGetSymbolAddress((void**)&xh, g_xh);   cudaGetSymbolAddress((void**)&xl, g_xl);
    cudaGetSymbolAddress((void**)&w0a, g_w0a); cudaGetSymbolAddress((void**)&w1a, g_w1a);
    cudaGetSymbolAddress((void**)&w0b, g_w0b); cudaGetSymbolAddress((void**)&w1b, g_w1b);
    cudaGetSymbolAddress((void**)&hh, g_hh);   cudaGetSymbolAddress((void**)&hl, g_hl);

    cudaFuncSetAttribute(gemm_mma<0, 1, true>,  cudaFuncAttributeMaxDynamicSharedMemorySize, GEMM_SMEM);
    cudaFuncSetAttribute(gemm_mma<2, 2, false>, cudaFuncAttributeMaxDynamicSharedMemorySize, GEMM_SMEM);

    // Launch order matters for ncu (-s 5 -c 1): #5 is the down GEMM.
    zero_cnt_kernel<<<1, 32>>>();                                   // 0
    gate_split_kernel<<<T_TOK / 8, 256>>>(x, Wg, xh, xl);           // 1

    {
        int n4 = FDIM * HDIM / 4;
        dim3 g(n4 / 256, 1, 2);
        splitW_kernel<<<g, 256>>>(W0a, w0a, W1a, w1a, n4);          // 2
        splitW_kernel<<<g, 256>>>(W0b, w0b, W1b, w1b, n4);          // 3
    }

    dim3 blk(256);
    dim3 gUp(FDIM / GBN, T_TOK / GBM, 2);   // (32, 64, 2), early-exit on n_e
    dim3 gDn(HDIM / GBN, T_TOK / GBM, 2);   // (16, 64, 2)

    // up-projection + activation -> h (fp16 hi/lo); both experts in one launch
    gemm_mma<0, 1, true><<<gUp, blk, GEMM_SMEM>>>(xh, xl, w0a, w1a, b0a, b1a,
                                                  nullptr, hh, hl, HDIM, FDIM); // 4
    // down-projection -> out (fp32); both experts, each token written once
    gemm_mma<2, 2, false><<<gDn, blk, GEMM_SMEM>>>(hh, hl, w0b, w1b, b0b, b1b,
                                                   out, nullptr, nullptr, FDIM, HDIM); // 5
}

// round 11
// speedup vs baseline: 8.1633x; 1.5860x over previous
#include <cuda_runtime.h>
#include <cuda_fp16.h>
#include <cstdint>
#include <math.h>

#define T_TOK 8192          // 4 * 2048 tokens
#define HDIM  2048
#define FDIM  4096          // 2*H

// ---------------- static device scratch (no allocs allowed) ----------------
__device__ int g_cnt[2];
__device__ int g_idx[2][T_TOK];
__device__ __half g_xh[(size_t)T_TOK * HDIM];
__device__ __half g_w0a[(size_t)FDIM * HDIM], g_w1a[(size_t)FDIM * HDIM];
__device__ __half g_w0b[(size_t)HDIM * FDIM], g_w1b[(size_t)HDIM * FDIM];
__device__ __half g_hh[(size_t)T_TOK * FDIM];

// ---------------- PTX helpers (base ISA only — no 'a'-gated features) ------
__device__ __forceinline__ uint32_t smem_u32(const void* p) {
    uint32_t a;
    asm("{ .reg .u64 t; cvta.to.shared.u64 t, %1; cvt.u32.u64 %0, t; }" : "=r"(a) : "l"(p));
    return a;
}
__device__ __forceinline__ void cp16(uint32_t dst, const void* src, uint32_t sz) {
    asm volatile("cp.async.cg.shared.global [%0], [%1], 16, %2;"
                 :: "r"(dst), "l"(src), "r"(sz) : "memory");
}
__device__ __forceinline__ void cp_commit() {
    asm volatile("cp.async.commit_group;" ::: "memory");
}
template <int N>
__device__ __forceinline__ void cp_wait() {
    asm volatile("cp.async.wait_group %0;" :: "n"(N) : "memory");
}
__device__ __forceinline__ void ldm4(uint32_t* r, uint32_t addr) {
    asm volatile("ldmatrix.sync.aligned.m8n8.x4.shared.b16 {%0,%1,%2,%3}, [%4];"
                 : "=r"(r[0]), "=r"(r[1]), "=r"(r[2]), "=r"(r[3]) : "r"(addr));
}
__device__ __forceinline__ void mma16816(float* d, const uint32_t* a, const uint32_t* b) {
    asm volatile(
        "mma.sync.aligned.m16n8k16.row.col.f32.f16.f16.f32 "
        "{%0,%1,%2,%3}, {%4,%5,%6,%7}, {%8,%9}, {%0,%1,%2,%3};"
        : "+f"(d[0]), "+f"(d[1]), "+f"(d[2]), "+f"(d[3])
        : "r"(a[0]), "r"(a[1]), "r"(a[2]), "r"(a[3]), "r"(b[0]), "r"(b[1]));
}
__device__ __forceinline__ uint32_t pack_h(__half a, __half b) {
    return (uint32_t)__half_as_ushort(a) | ((uint32_t)__half_as_ushort(b) << 16);
}

// ---------------- small kernels ---------------------------------------------
__global__ void zero_cnt_kernel() {
    if (threadIdx.x < 2) g_cnt[threadIdx.x] = 0;
}

// Fused gate + fp16 convert of x. One warp per token. argmax over 2 logits
// (softmax monotone; tie -> expert 0, matching jnp.argmax-first).
__global__ void gate_split_kernel(const float* __restrict__ x,
                                  const float* __restrict__ Wg,
                                  __half* __restrict__ xh) {
    __shared__ float swg[2 * HDIM];
    int tid = threadIdx.x;
    for (int i = tid; i < 2 * HDIM; i += blockDim.x) swg[i] = Wg[i];
    __syncthreads();
    int warp = tid >> 5, lane = tid & 31;
    int tok = blockIdx.x * 8 + warp;
    size_t rowOff = (size_t)tok * HDIM;
    const float4* xr = (const float4*)(x + rowOff);
    uint2* hh = (uint2*)(xh + rowOff);

    float a0 = 0.f, a1 = 0.f;
#pragma unroll
    for (int j = 0; j < HDIM / 128; ++j) {        // 16 iters of float4 per lane
        int i4 = lane + 32 * j;
        float4 v = xr[i4];
        int k = i4 * 4;
        a0 = fmaf(v.x, swg[k], fmaf(v.y, swg[k + 1], fmaf(v.z, swg[k + 2], fmaf(v.w, swg[k + 3], a0))));
        a1 = fmaf(v.x, swg[HDIM + k], fmaf(v.y, swg[HDIM + k + 1],
             fmaf(v.z, swg[HDIM + k + 2], fmaf(v.w, swg[HDIM + k + 3], a1))));
        hh[i4] = make_uint2(pack_h(__float2half(v.x), __float2half(v.y)),
                            pack_h(__float2half(v.z), __float2half(v.w)));
    }
#pragma unroll
    for (int o = 16; o; o >>= 1) {
        a0 += __shfl_xor_sync(0xffffffffu, a0, o);
        a1 += __shfl_xor_sync(0xffffffffu, a1, o);
    }
    if (lane == 0) {
        int e = (a1 > a0) ? 1 : 0;
        int pos = atomicAdd(&g_cnt[e], 1);
        g_idx[e][pos] = tok;
    }
}

// fp32 -> fp16 weight convert; blockIdx.z selects which of two tensors.
__global__ void splitW_kernel(const float* __restrict__ s0, __half* __restrict__ d0,
                              const float* __restrict__ s1, __half* __restrict__ d1,
                              int n4) {
    int i = blockIdx.x * blockDim.x + threadIdx.x;
    if (i >= n4) return;
    const float* src = blockIdx.z ? s1 : s0;
    __half* dst = blockIdx.z ? d1 : d0;
    float4 v = ((const float4*)src)[i];
    ((uint2*)dst)[i] = make_uint2(pack_h(__float2half(v.x), __float2half(v.y)),
                                  pack_h(__float2half(v.z), __float2half(v.w)));
}

template <int ACT>
__device__ __forceinline__ float act_fn(float v) {
    if (ACT == 0) return 0.5f * v * (1.0f + erff(v * 0.70710678118654752440f)); // exact GELU
    if (ACT == 1) return fmaxf(v, 0.0f);                                        // ReLU
    return v;
}

// ---------------- mma.sync gathered GEMM ------------------------------------
// C[tok, n] = act_e( sum_k A[tok,k]*B_e[n,k] + bias_e[n] ), e = blockIdx.z,
// A rows via g_idx[e]. Single-term fp16 (A, B both fp16; fp32 accum).
// CTA tile 128x128, BK=64, 8 warps (2M x 4N), warp tile 64x32.
// Smem per stage: A/B, 128 rows x 128B each (32 KB); 3 stages, 2 CTA/SM.
static constexpr int GBM = 128, GBN = 128, GBK = 64;
static constexpr uint32_t STAGE_BYTES = 2 * 128 * 128;       // 32 KB
static constexpr uint32_t GEMM_SMEM = 3 * STAGE_BYTES;       // 96 KB dynamic

// ACT0/ACT1: activation for expert0/expert1 (up: GELU/ReLU; down: none/none)
template <int ACT0, int ACT1, bool HALF_OUT>
__global__ void __launch_bounds__(256, 2)
gemm_mma(const __half* __restrict__ A,
         const __half* __restrict__ B0, const __half* __restrict__ B1,
         const float* __restrict__ bias0, const float* __restrict__ bias1,
         float* __restrict__ Cf, __half* __restrict__ Ch,
         int K, int ldc) {
    extern __shared__ char dyn_smem[];
    __shared__ int   sTok[GBM];
    __shared__ float sBias[GBN];

    const int expert = blockIdx.z;
    const int n_e = g_cnt[expert];
    const int mBase = blockIdx.y * GBM;
    if (mBase >= n_e) return;
    const int nBase = blockIdx.x * GBN;
    const __half* B = expert ? B1 : B0;
    const float* bias = expert ? bias1 : bias0;
    const uint32_t sb = smem_u32(dyn_smem);
    const int tid = threadIdx.x;

    if (tid < GBM) {
        int r = mBase + tid;
        sTok[tid] = (r < n_e) ? g_idx[expert][r] : -1;
    }
    if (tid < GBN) sBias[tid] = bias[nBase + tid];
    __syncthreads();

    const int nCh = K / GBK;

    // 1024 16B-chunks per matrix; row = i>>3, c = i&7, swizzle c^(row&7)
    auto load_stage = [&](int c, int buf) {
        const int kOff = c * GBK;
        const uint32_t aS = sb + buf * STAGE_BYTES;
        const uint32_t bS = aS + 16384;
#pragma unroll
        for (int it = 0; it < 4; ++it) {
            int i = tid + it * 256;
            int row = i >> 3, cc = i & 7;
            uint32_t so = (uint32_t)(row * 128 + ((cc ^ (row & 7)) << 4));
            int tok = sTok[row];
            uint32_t sz = (tok >= 0) ? 16u : 0u;
            int tokc = (tok >= 0) ? tok : 0;
            const char* pA = (const char*)(A + (size_t)tokc * K + kOff) + cc * 16;
            cp16(aS + so, pA, sz);
            const char* pB = (const char*)(B + (size_t)(nBase + row) * K + kOff) + cc * 16;
            cp16(bS + so, pB, 16u);
        }
        cp_commit();
    };

    // fragment lane mapping
    const int lane = tid & 31;
    const int wid = tid >> 5;
    const int wm = wid & 1;       // M
    const int wn = wid >> 1;      // N
    const int aRow = lane & 15;
    const int aSel = (lane >> 4) & 1;
    const int aSw  = aRow & 7;
    const int bRow = (lane & 7) + ((lane >> 4) & 1) * 8;
    const int bSel = (lane >> 3) & 1;
    const int bSw  = bRow & 7;

    uint32_t aRowByte[4], bRowByte[2];
#pragma unroll
    for (int mi = 0; mi < 4; ++mi) aRowByte[mi] = (uint32_t)((wm * 64 + mi * 16 + aRow) * 128);
#pragma unroll
    for (int nb = 0; nb < 2; ++nb) bRowByte[nb] = (uint32_t)((wn * 32 + nb * 16 + bRow) * 128);

    float acc[4][4][4];
#pragma unroll
    for (int mi = 0; mi < 4; ++mi)
#pragma unroll
        for (int ni = 0; ni < 4; ++ni)
#pragma unroll
            for (int q = 0; q < 4; ++q) acc[mi][ni][q] = 0.f;

    // 3-stage pipeline
    load_stage(0, 0);
    load_stage(1, 1);
    for (int c = 0; c < nCh; ++c) {
        if (c + 2 < nCh) {
            load_stage(c + 2, (c + 2) % 3);
            cp_wait<2>();
        } else {
            cp_wait<0>();
        }
        __syncthreads();

        const uint32_t aS = sb + (c % 3) * STAGE_BYTES;
        const uint32_t bS = aS + 16384;

#pragma unroll
        for (int ks = 0; ks < GBK / 16; ++ks) {
            const int kc = ks * 2;
            const uint32_t aOff = (uint32_t)(((kc + aSel) ^ aSw) << 4);
            const uint32_t bOff = (uint32_t)(((kc + bSel) ^ bSw) << 4);
            uint32_t bh[2][4];
#pragma unroll
            for (int nb = 0; nb < 2; ++nb) ldm4(bh[nb], bS + bRowByte[nb] + bOff);
#pragma unroll
            for (int mi = 0; mi < 4; ++mi) {
                uint32_t af[4];
                ldm4(af, aS + aRowByte[mi] + aOff);
#pragma unroll
                for (int nb = 0; nb < 2; ++nb)
#pragma unroll
                    for (int h = 0; h < 2; ++h)
                        mma16816(acc[mi][nb * 2 + h], af, &bh[nb][h * 2]);
            }
        }
        __syncthreads();
    }

    // epilogue: d0,d1 -> (m = lane/4, n = 2*(lane%4)); d2,d3 -> m+8
    const int mrow = lane >> 2;
    const int ncol = 2 * (lane & 3);
#pragma unroll
    for (int mi = 0; mi < 4; ++mi) {
#pragma unroll
        for (int ni = 0; ni < 4; ++ni) {
            int colLoc = wn * 32 + ni * 8 + ncol;
            int col = nBase + colLoc;
            float bv0 = sBias[colLoc], bv1 = sBias[colLoc + 1];
            int rLoc = wm * 64 + mi * 16 + mrow;
            int tok0 = sTok[rLoc], tok1 = sTok[rLoc + 8];
#pragma unroll
            for (int half = 0; half < 2; ++half) {
                int tok = half ? tok1 : tok0;
                if (tok < 0) continue;
                float r0 = acc[mi][ni][half * 2 + 0] + bv0;
                float r1 = acc[mi][ni][half * 2 + 1] + bv1;
                float v0 = expert ? act_fn<ACT1>(r0) : act_fn<ACT0>(r0);
                float v1 = expert ? act_fn<ACT1>(r1) : act_fn<ACT0>(r1);
                size_t base = (size_t)tok * ldc + col;
                if (HALF_OUT) {
                    *(uint32_t*)(Ch + base) = pack_h(__float2half(v0), __float2half(v1));
                } else {
                    *(float2*)(Cf + base) = make_float2(v0, v1);
                }
            }
        }
    }
}

// ---------------- launch -----------------------------------------------------
extern "C" void kernel_launch(void* const* d_in, const int* in_sizes, int n_in,
                              void* d_out, int out_size) {
    (void)in_sizes; (void)n_in; (void)out_size;
    const float* x   = (const float*)d_in[0];
    const float* Wg  = (const float*)d_in[1];
    const float* W0a = (const float*)d_in[2];
    const float* b0a = (const float*)d_in[3];
    const float* W0b = (const float*)d_in[4];
    const float* b0b = (const float*)d_in[5];
    const float* W1a = (const float*)d_in[6];
    const float* b1a = (const float*)d_in[7];
    const float* W1b = (const float*)d_in[8];
    const float* b1b = (const float*)d_in[9];
    float* out = (float*)d_out;

    __half *xh, *w0a, *w1a, *w0b, *w1b, *hh;
    cudaGetSymbolAddress((void**)&xh, g_xh);
    cudaGetSymbolAddress((void**)&w0a, g_w0a); cudaGetSymbolAddress((void**)&w1a, g_w1a);
    cudaGetSymbolAddress((void**)&w0b, g_w0b); cudaGetSymbolAddress((void**)&w1b, g_w1b);
    cudaGetSymbolAddress((void**)&hh, g_hh);

    cudaFuncSetAttribute(gemm_mma<0, 1, true>,  cudaFuncAttributeMaxDynamicSharedMemorySize, GEMM_SMEM);
    cudaFuncSetAttribute(gemm_mma<2, 2, false>, cudaFuncAttributeMaxDynamicSharedMemorySize, GEMM_SMEM);

    zero_cnt_kernel<<<1, 32>>>();
    gate_split_kernel<<<T_TOK / 8, 256>>>(x, Wg, xh);

    {
        int n4 = FDIM * HDIM / 4;
        dim3 g(n4 / 256, 1, 2);
        splitW_kernel<<<g, 256>>>(W0a, w0a, W1a, w1a, n4);
        splitW_kernel<<<g, 256>>>(W0b, w0b, W1b, w1b, n4);
    }

    dim3 blk(256);
    dim3 gUp(FDIM / GBN, T_TOK / GBM, 2);   // (32, 64, 2), early-exit on n_e
    dim3 gDn(HDIM / GBN, T_TOK / GBM, 2);   // (16, 64, 2)

    // up-projection + activation -> h (fp16); both experts in one launch
    gemm_mma<0, 1, true><<<gUp, blk, GEMM_SMEM>>>(xh, w0a, w1a, b0a, b1a,
                                                  nullptr, hh, HDIM, FDIM);
    // down-projection -> out (fp32); both experts, each token written once
    gemm_mma<2, 2, false><<<gDn, blk, GEMM_SMEM>>>(hh, w0b, w1b, b0b, b1b,
                                                   out, nullptr, FDIM, HDIM);
}

// round 12
// speedup vs baseline: 8.1670x; 1.0005x over previous
#include <cuda_runtime.h>
#include <cuda_fp16.h>
#include <cstdint>
#include <math.h>

#define T_TOK 8192          // 4 * 2048 tokens
#define HDIM  2048
#define FDIM  4096          // 2*H

// ---------------- static device scratch (no allocs allowed) ----------------
__device__ int g_cnt[2];
__device__ int g_idx[2][T_TOK];
__device__ __half g_xh[(size_t)T_TOK * HDIM];
__device__ __half g_w0a[(size_t)FDIM * HDIM], g_w1a[(size_t)FDIM * HDIM];
__device__ __half g_w0b[(size_t)HDIM * FDIM], g_w1b[(size_t)HDIM * FDIM];
__device__ __half g_hh[(size_t)T_TOK * FDIM];

// ---------------- PTX helpers (base ISA only — no 'a'-gated features) ------
__device__ __forceinline__ uint32_t smem_u32(const void* p) {
    uint32_t a;
    asm("{ .reg .u64 t; cvta.to.shared.u64 t, %1; cvt.u32.u64 %0, t; }" : "=r"(a) : "l"(p));
    return a;
}
__device__ __forceinline__ void cp16(uint32_t dst, const void* src, uint32_t sz) {
    asm volatile("cp.async.cg.shared.global [%0], [%1], 16, %2;"
                 :: "r"(dst), "l"(src), "r"(sz) : "memory");
}
__device__ __forceinline__ void cp_commit() {
    asm volatile("cp.async.commit_group;" ::: "memory");
}
template <int N>
__device__ __forceinline__ void cp_wait() {
    asm volatile("cp.async.wait_group %0;" :: "n"(N) : "memory");
}
__device__ __forceinline__ void ldm4(uint32_t* r, uint32_t addr) {
    asm volatile("ldmatrix.sync.aligned.m8n8.x4.shared.b16 {%0,%1,%2,%3}, [%4];"
                 : "=r"(r[0]), "=r"(r[1]), "=r"(r[2]), "=r"(r[3]) : "r"(addr));
}
__device__ __forceinline__ void mma16816(float* d, const uint32_t* a, const uint32_t* b) {
    asm volatile(
        "mma.sync.aligned.m16n8k16.row.col.f32.f16.f16.f32 "
        "{%0,%1,%2,%3}, {%4,%5,%6,%7}, {%8,%9}, {%0,%1,%2,%3};"
        : "+f"(d[0]), "+f"(d[1]), "+f"(d[2]), "+f"(d[3])
        : "r"(a[0]), "r"(a[1]), "r"(a[2]), "r"(a[3]), "r"(b[0]), "r"(b[1]));
}
__device__ __forceinline__ uint32_t pack_h(__half a, __half b) {
    return (uint32_t)__half_as_ushort(a) | ((uint32_t)__half_as_ushort(b) << 16);
}

// ---------------- small kernels ---------------------------------------------
__global__ void zero_cnt_kernel() {
    if (threadIdx.x < 2) g_cnt[threadIdx.x] = 0;
}

// Fused gate + fp16 convert of x. One warp per token. argmax over 2 logits
// (softmax monotone; tie -> expert 0, matching jnp.argmax-first).
__global__ void gate_split_kernel(const float* __restrict__ x,
                                  const float* __restrict__ Wg,
                                  __half* __restrict__ xh) {
    __shared__ float swg[2 * HDIM];
    int tid = threadIdx.x;
    for (int i = tid; i < 2 * HDIM; i += blockDim.x) swg[i] = Wg[i];
    __syncthreads();
    int warp = tid >> 5, lane = tid & 31;
    int tok = blockIdx.x * 8 + warp;
    size_t rowOff = (size_t)tok * HDIM;
    const float4* xr = (const float4*)(x + rowOff);
    uint2* hh = (uint2*)(xh + rowOff);

    float a0 = 0.f, a1 = 0.f;
#pragma unroll
    for (int j = 0; j < HDIM / 128; ++j) {        // 16 iters of float4 per lane
        int i4 = lane + 32 * j;
        float4 v = xr[i4];
        int k = i4 * 4;
        a0 = fmaf(v.x, swg[k], fmaf(v.y, swg[k + 1], fmaf(v.z, swg[k + 2], fmaf(v.w, swg[k + 3], a0))));
        a1 = fmaf(v.x, swg[HDIM + k], fmaf(v.y, swg[HDIM + k + 1],
             fmaf(v.z, swg[HDIM + k + 2], fmaf(v.w, swg[HDIM + k + 3], a1))));
        hh[i4] = make_uint2(pack_h(__float2half(v.x), __float2half(v.y)),
                            pack_h(__float2half(v.z), __float2half(v.w)));
    }
#pragma unroll
    for (int o = 16; o; o >>= 1) {
        a0 += __shfl_xor_sync(0xffffffffu, a0, o);
        a1 += __shfl_xor_sync(0xffffffffu, a1, o);
    }
    if (lane == 0) {
        int e = (a1 > a0) ? 1 : 0;
        int pos = atomicAdd(&g_cnt[e], 1);
        g_idx[e][pos] = tok;
    }
}

// fp32 -> fp16 weight convert; blockIdx.z selects which of two tensors.
__global__ void splitW_kernel(const float* __restrict__ s0, __half* __restrict__ d0,
                              const float* __restrict__ s1, __half* __restrict__ d1,
                              int n4) {
    int i = blockIdx.x * blockDim.x + threadIdx.x;
    if (i >= n4) return;
    const float* src = blockIdx.z ? s1 : s0;
    __half* dst = blockIdx.z ? d1 : d0;
    float4 v = ((const float4*)src)[i];
    ((uint2*)dst)[i] = make_uint2(pack_h(__float2half(v.x), __float2half(v.y)),
                                  pack_h(__float2half(v.z), __float2half(v.w)));
}

template <int ACT>
__device__ __forceinline__ float act_fn(float v) {
    if (ACT == 0) return 0.5f * v * (1.0f + erff(v * 0.70710678118654752440f)); // exact GELU
    if (ACT == 1) return fmaxf(v, 0.0f);                                        // ReLU
    return v;
}

// ---------------- mma.sync gathered GEMM ------------------------------------
// C[tok, n] = act_e( sum_k A[tok,k]*B_e[n,k] + bias_e[n] ), e = blockIdx.z,
// A rows via g_idx[e]. Single-term fp16 (A, B both fp16; fp32 accum).
// CTA tile 128x128, BK=64, 8 warps (2M x 4N), warp tile 64x32.
// Smem per stage: A/B, 128 rows x 128B each (32 KB); 3 stages, 2 CTA/SM.
static constexpr int GBM = 128, GBN = 128, GBK = 64;
static constexpr uint32_t STAGE_BYTES = 2 * 128 * 128;       // 32 KB
static constexpr uint32_t GEMM_SMEM = 3 * STAGE_BYTES;       // 96 KB dynamic

// ACT0/ACT1: activation for expert0/expert1 (up: GELU/ReLU; down: none/none)
template <int ACT0, int ACT1, bool HALF_OUT>
__global__ void __launch_bounds__(256, 2)
gemm_mma(const __half* __restrict__ A,
         const __half* __restrict__ B0, const __half* __restrict__ B1,
         const float* __restrict__ bias0, const float* __restrict__ bias1,
         float* __restrict__ Cf, __half* __restrict__ Ch,
         int K, int ldc) {
    extern __shared__ char dyn_smem[];
    __shared__ int   sTok[GBM];
    __shared__ float sBias[GBN];

    const int expert = blockIdx.z;
    const int n_e = g_cnt[expert];
    const int mBase = blockIdx.y * GBM;
    if (mBase >= n_e) return;
    const int nBase = blockIdx.x * GBN;
    const __half* B = expert ? B1 : B0;
    const float* bias = expert ? bias1 : bias0;
    const uint32_t sb = smem_u32(dyn_smem);
    const int tid = threadIdx.x;

    if (tid < GBM) {
        int r = mBase + tid;
        sTok[tid] = (r < n_e) ? g_idx[expert][r] : -1;
    }
    if (tid < GBN) sBias[tid] = bias[nBase + tid];
    __syncthreads();

    const int nCh = K / GBK;

    // 1024 16B-chunks per matrix; row = i>>3, c = i&7, swizzle c^(row&7)
    auto load_stage = [&](int c, int buf) {
        const int kOff = c * GBK;
        const uint32_t aS = sb + buf * STAGE_BYTES;
        const uint32_t bS = aS + 16384;
#pragma unroll
        for (int it = 0; it < 4; ++it) {
            int i = tid + it * 256;
            int row = i >> 3, cc = i & 7;
            uint32_t so = (uint32_t)(row * 128 + ((cc ^ (row & 7)) << 4));
            int tok = sTok[row];
            uint32_t sz = (tok >= 0) ? 16u : 0u;
            int tokc = (tok >= 0) ? tok : 0;
            const char* pA = (const char*)(A + (size_t)tokc * K + kOff) + cc * 16;
            cp16(aS + so, pA, sz);
            const char* pB = (const char*)(B + (size_t)(nBase + row) * K + kOff) + cc * 16;
            cp16(bS + so, pB, 16u);
        }
        cp_commit();
    };

    // fragment lane mapping
    const int lane = tid & 31;
    const int wid = tid >> 5;
    const int wm = wid & 1;       // M
    const int wn = wid >> 1;      // N
    const int aRow = lane & 15;
    const int aSel = (lane >> 4) & 1;
    const int aSw  = aRow & 7;
    const int bRow = (lane & 7) + ((lane >> 4) & 1) * 8;
    const int bSel = (lane >> 3) & 1;
    const int bSw  = bRow & 7;

    uint32_t aRowByte[4], bRowByte[2];
#pragma unroll
    for (int mi = 0; mi < 4; ++mi) aRowByte[mi] = (uint32_t)((wm * 64 + mi * 16 + aRow) * 128);
#pragma unroll
    for (int nb = 0; nb < 2; ++nb) bRowByte[nb] = (uint32_t)((wn * 32 + nb * 16 + bRow) * 128);

    float acc[4][4][4];
#pragma unroll
    for (int mi = 0; mi < 4; ++mi)
#pragma unroll
        for (int ni = 0; ni < 4; ++ni)
#pragma unroll
            for (int q = 0; q < 4; ++q) acc[mi][ni][q] = 0.f;

    // 3-stage pipeline
    load_stage(0, 0);
    load_stage(1, 1);
    for (int c = 0; c < nCh; ++c) {
        if (c + 2 < nCh) {
            load_stage(c + 2, (c + 2) % 3);
            cp_wait<2>();
        } else {
            cp_wait<0>();
        }
        __syncthreads();

        const uint32_t aS = sb + (c % 3) * STAGE_BYTES;
        const uint32_t bS = aS + 16384;

#pragma unroll
        for (int ks = 0; ks < GBK / 16; ++ks) {
            const int kc = ks * 2;
            const uint32_t aOff = (uint32_t)(((kc + aSel) ^ aSw) << 4);
            const uint32_t bOff = (uint32_t)(((kc + bSel) ^ bSw) << 4);
            uint32_t bh[2][4];
#pragma unroll
            for (int nb = 0; nb < 2; ++nb) ldm4(bh[nb], bS + bRowByte[nb] + bOff);
#pragma unroll
            for (int mi = 0; mi < 4; ++mi) {
                uint32_t af[4];
                ldm4(af, aS + aRowByte[mi] + aOff);
#pragma unroll
                for (int nb = 0; nb < 2; ++nb)
#pragma unroll
                    for (int h = 0; h < 2; ++h)
                        mma16816(acc[mi][nb * 2 + h], af, &bh[nb][h * 2]);
            }
        }
        __syncthreads();
    }

    // epilogue: d0,d1 -> (m = lane/4, n = 2*(lane%4)); d2,d3 -> m+8
    const int mrow = lane >> 2;
    const int ncol = 2 * (lane & 3);
#pragma unroll
    for (int mi = 0; mi < 4; ++mi) {
#pragma unroll
        for (int ni = 0; ni < 4; ++ni) {
            int colLoc = wn * 32 + ni * 8 + ncol;
            int col = nBase + colLoc;
            float bv0 = sBias[colLoc], bv1 = sBias[colLoc + 1];
            int rLoc = wm * 64 + mi * 16 + mrow;
            int tok0 = sTok[rLoc], tok1 = sTok[rLoc + 8];
#pragma unroll
            for (int half = 0; half < 2; ++half) {
                int tok = half ? tok1 : tok0;
                if (tok < 0) continue;
                float r0 = acc[mi][ni][half * 2 + 0] + bv0;
                float r1 = acc[mi][ni][half * 2 + 1] + bv1;
                float v0 = expert ? act_fn<ACT1>(r0) : act_fn<ACT0>(r0);
                float v1 = expert ? act_fn<ACT1>(r1) : act_fn<ACT0>(r1);
                size_t base = (size_t)tok * ldc + col;
                if (HALF_OUT) {
                    *(uint32_t*)(Ch + base) = pack_h(__float2half(v0), __float2half(v1));
                } else {
                    *(float2*)(Cf + base) = make_float2(v0, v1);
                }
            }
        }
    }
}

// ---------------- launch -----------------------------------------------------
extern "C" void kernel_launch(void* const* d_in, const int* in_sizes, int n_in,
                              void* d_out, int out_size) {
    (void)in_sizes; (void)n_in; (void)out_size;
    const float* x   = (const float*)d_in[0];
    const float* Wg  = (const float*)d_in[1];
    const float* W0a = (const float*)d_in[2];
    const float* b0a = (const float*)d_in[3];
    const float* W0b = (const float*)d_in[4];
    const float* b0b = (const float*)d_in[5];
    const float* W1a = (const float*)d_in[6];
    const float* b1a = (const float*)d_in[7];
    const float* W1b = (const float*)d_in[8];
    const float* b1b = (const float*)d_in[9];
    float* out = (float*)d_out;

    __half *xh, *w0a, *w1a, *w0b, *w1b, *hh;
    cudaGetSymbolAddress((void**)&xh, g_xh);
    cudaGetSymbolAddress((void**)&w0a, g_w0a); cudaGetSymbolAddress((void**)&w1a, g_w1a);
    cudaGetSymbolAddress((void**)&w0b, g_w0b); cudaGetSymbolAddress((void**)&w1b, g_w1b);
    cudaGetSymbolAddress((void**)&hh, g_hh);

    cudaFuncSetAttribute(gemm_mma<0, 1, true>,  cudaFuncAttributeMaxDynamicSharedMemorySize, GEMM_SMEM);
    cudaFuncSetAttribute(gemm_mma<2, 2, false>, cudaFuncAttributeMaxDynamicSharedMemorySize, GEMM_SMEM);

    zero_cnt_kernel<<<1, 32>>>();
    gate_split_kernel<<<T_TOK / 8, 256>>>(x, Wg, xh);

    {
        int n4 = FDIM * HDIM / 4;
        dim3 g(n4 / 256, 1, 2);
        splitW_kernel<<<g, 256>>>(W0a, w0a, W1a, w1a, n4);
        splitW_kernel<<<g, 256>>>(W0b, w0b, W1b, w1b, n4);
    }

    dim3 blk(256);
    dim3 gUp(FDIM / GBN, T_TOK / GBM, 2);   // (32, 64, 2), early-exit on n_e
    dim3 gDn(HDIM / GBN, T_TOK / GBM, 2);   // (16, 64, 2)

    // up-projection + activation -> h (fp16); both experts in one launch
    gemm_mma<0, 1, true><<<gUp, blk, GEMM_SMEM>>>(xh, w0a, w1a, b0a, b1a,
                                                  nullptr, hh, HDIM, FDIM);
    // down-projection -> out (fp32); both experts, each token written once
    gemm_mma<2, 2, false><<<gDn, blk, GEMM_SMEM>>>(hh, w0b, w1b, b0b, b1b,
                                                   out, nullptr, FDIM, HDIM);
}